// round 8
// baseline (speedup 1.0000x reference)
#include <cuda_runtime.h>
#include <cuda_bf16.h>
#include <math.h>
#include <stdint.h>

// GridGRU: N=32, T=512, D=1024, H=1024
// inputs: x (N,T,D), prev_ht (N,H), weight (2048,6144), bias (6144)
// outputs: h (N,T,D) then last_ht (N,H), concatenated in d_out.

#define NN 32
#define TT 512
#define DD 1024
#define HH 1024
#define MROWS (NN*TT)        // 16384
#define WLD 6144
#define GK2 40               // gemm smem k stride (bf16)
#define WSP 1032             // scan weight smem k stride
#define HSP2 136             // scan activation smem k stride (128 + 8)
#define NB1 64               // phase-1 blocks (gate GEMM, 32 cols each)
#define NB2 32               // phase-2 blocks (candidate GEMM, 32 cols each)

// ---------------- scratch (device globals) -----------------------------------
__device__ float g_gates[(size_t)MROWS * 3072];        // 192 MB
__device__ float g_hcur[NN * HH];
__device__ float g_U[NN * HH];
__device__ float g_UD[(size_t)MROWS * DD];             // 64 MB
__device__ __nv_bfloat16 g_Wt_hi[(size_t)6144 * 2048]; // transposed [col][k]
__device__ __nv_bfloat16 g_Wt_lo[(size_t)6144 * 2048];
__device__ __nv_bfloat16 g_X_hi[(size_t)MROWS * DD], g_X_lo[(size_t)MROWS * DD];
__device__ __nv_bfloat16 g_HT_hi[(size_t)MROWS * HH], g_HT_lo[(size_t)MROWS * HH];
__device__ __nv_bfloat16 g_RX_hi[(size_t)MROWS * DD], g_RX_lo[(size_t)MROWS * DD];
__device__ __nv_bfloat16 g_h_hi[NN * HH], g_h_lo[NN * HH];
__device__ __nv_bfloat16 g_rh_hi[NN * HH], g_rh_lo[NN * HH];
__device__ unsigned g_cntA, g_cntB;

__device__ __forceinline__ void mma16816(float* c, const uint32_t* a, const uint32_t* b)
{
    asm volatile(
        "mma.sync.aligned.m16n8k16.row.col.f32.bf16.bf16.f32 "
        "{%0,%1,%2,%3}, {%4,%5,%6,%7}, {%8,%9}, {%0,%1,%2,%3};\n"
        : "+f"(c[0]), "+f"(c[1]), "+f"(c[2]), "+f"(c[3])
        : "r"(a[0]), "r"(a[1]), "r"(a[2]), "r"(a[3]), "r"(b[0]), "r"(b[1]));
}

__device__ __forceinline__ void cpa16(void* smem, const void* g)
{
    uint32_t a = (uint32_t)__cvta_generic_to_shared(smem);
    asm volatile("cp.async.cg.shared.global [%0], [%1], 16;" :: "r"(a), "l"(g));
}
#define CPA_COMMIT asm volatile("cp.async.commit_group;" ::: "memory")
#define CPA_WAIT(n) asm volatile("cp.async.wait_group %0;" :: "n"(n) : "memory")

__device__ __forceinline__ void rel_add(unsigned* p)
{
    asm volatile("red.release.gpu.global.add.u32 [%0], 1;" :: "l"(p) : "memory");
}
__device__ __forceinline__ unsigned acq_ld(const unsigned* p)
{
    unsigned v;
    asm volatile("ld.acquire.gpu.global.u32 %0, [%1];" : "=r"(v) : "l"(p) : "memory");
    return v;
}

// ---------------- prep: split x to bf16 hi/lo --------------------------------
__global__ void conv_x_kernel(const float* __restrict__ x)
{
    long i = ((long)blockIdx.x * 256 + threadIdx.x) * 8;
    float4 v0 = *(const float4*)(x + i);
    float4 v1 = *(const float4*)(x + i + 4);
    float v[8] = {v0.x, v0.y, v0.z, v0.w, v1.x, v1.y, v1.z, v1.w};
    __align__(16) __nv_bfloat16 hb[8], lb[8];
#pragma unroll
    for (int e = 0; e < 8; e++) {
        __nv_bfloat16 h = __float2bfloat16(v[e]);
        hb[e] = h;
        lb[e] = __float2bfloat16(v[e] - __bfloat162float(h));
    }
    *(uint4*)&g_X_hi[i] = *(uint4*)hb;
    *(uint4*)&g_X_lo[i] = *(uint4*)lb;
}

// ---------------- prep: split + transpose weight to [col][k] bf16 ------------
__global__ void conv_w_kernel(const float* __restrict__ W)
{
    __shared__ float ws[64][65];
    const int k0 = blockIdx.x * 64, c0 = blockIdx.y * 64;
    const int tid = threadIdx.x;
#pragma unroll
    for (int s = 0; s < 4; s++) {
        int f = tid + s * 256;
        int kr = f >> 4, cc = (f & 15) * 4;
        float4 v = *(const float4*)(W + (long)(k0 + kr) * WLD + c0 + cc);
        ws[kr][cc] = v.x; ws[kr][cc + 1] = v.y; ws[kr][cc + 2] = v.z; ws[kr][cc + 3] = v.w;
    }
    __syncthreads();
    const int col = tid & 63, kq = tid >> 6;
    __align__(16) __nv_bfloat16 hb[16], lb[16];
#pragma unroll
    for (int j = 0; j < 16; j++) {
        float v = ws[kq * 16 + j][col];
        __nv_bfloat16 h = __float2bfloat16(v);
        hb[j] = h;
        lb[j] = __float2bfloat16(v - __bfloat162float(h));
    }
    long dst = (long)(c0 + col) * 2048 + k0 + kq * 16;
    ((uint4*)&g_Wt_hi[dst])[0] = ((uint4*)hb)[0];
    ((uint4*)&g_Wt_hi[dst])[1] = ((uint4*)hb)[1];
    ((uint4*)&g_Wt_lo[dst])[0] = ((uint4*)lb)[0];
    ((uint4*)&g_Wt_lo[dst])[1] = ((uint4*)lb)[1];
}

// ---------------- big GEMM: bf16 hi/lo, cp.async double-buffer ---------------
template<int EPI>
__global__ void __launch_bounds__(256, 2)
mma_gemm(const __nv_bfloat16* __restrict__ A0h, const __nv_bfloat16* __restrict__ A0l,
         const __nv_bfloat16* __restrict__ A1h, const __nv_bfloat16* __restrict__ A1l,
         const __nv_bfloat16* __restrict__ Bth, const __nv_bfloat16* __restrict__ Btl,
         const float* __restrict__ bias, const float* __restrict__ X,
         float* __restrict__ out, const float* __restrict__ UD,
         int K, int ldc)
{
    extern __shared__ __align__(16) char gsm[];
    __nv_bfloat16* As = (__nv_bfloat16*)gsm;        // [stage][hi/lo][128*GK2]
    __nv_bfloat16* Bs = As + 2 * 2 * 128 * GK2;

    const int tid = threadIdx.x, lane = tid & 31, warp = tid >> 5;
    const int warpM = warp & 1, warpN = warp >> 1;
    const int g = lane >> 2, tig = lane & 3;
    const int row0 = blockIdx.y * 128, col0 = blockIdx.x * 128;
    const int rA = warpM * 64, cB = warpN * 32;
    const int r0 = tid >> 2, kq = (tid & 3) * 8;
    const int r1 = r0 + 64;

    float acc[4][4][4];
#pragma unroll
    for (int i = 0; i < 4; i++)
#pragma unroll
        for (int j = 0; j < 4; j++)
#pragma unroll
            for (int e = 0; e < 4; e++) acc[i][j][e] = 0.f;

    auto ISSUE = [&](int k0, int st) {
        const __nv_bfloat16 *ph, *pl; int kb;
        if (k0 < 1024) { ph = A0h; pl = A0l; kb = k0; }
        else           { ph = A1h; pl = A1l; kb = k0 - 1024; }
        __nv_bfloat16* Ah = As + (st * 2 + 0) * 128 * GK2;
        __nv_bfloat16* Al = As + (st * 2 + 1) * 128 * GK2;
        __nv_bfloat16* Bh = Bs + (st * 2 + 0) * 128 * GK2;
        __nv_bfloat16* Bl = Bs + (st * 2 + 1) * 128 * GK2;
        cpa16(Ah + r0 * GK2 + kq, ph + (long)(row0 + r0) * 1024 + kb + kq);
        cpa16(Ah + r1 * GK2 + kq, ph + (long)(row0 + r1) * 1024 + kb + kq);
        cpa16(Al + r0 * GK2 + kq, pl + (long)(row0 + r0) * 1024 + kb + kq);
        cpa16(Al + r1 * GK2 + kq, pl + (long)(row0 + r1) * 1024 + kb + kq);
        cpa16(Bh + r0 * GK2 + kq, Bth + (long)(col0 + r0) * 2048 + k0 + kq);
        cpa16(Bh + r1 * GK2 + kq, Bth + (long)(col0 + r1) * 2048 + k0 + kq);
        cpa16(Bl + r0 * GK2 + kq, Btl + (long)(col0 + r0) * 2048 + k0 + kq);
        cpa16(Bl + r1 * GK2 + kq, Btl + (long)(col0 + r1) * 2048 + k0 + kq);
    };

    const int KT = K / 32;
    ISSUE(0, 0); CPA_COMMIT;

    for (int kt = 0; kt < KT; kt++) {
        const int st = kt & 1;
        if (kt + 1 < KT) { ISSUE((kt + 1) * 32, st ^ 1); CPA_COMMIT; CPA_WAIT(1); }
        else             { CPA_WAIT(0); }
        __syncthreads();

        const __nv_bfloat16* Ah = As + (st * 2 + 0) * 128 * GK2;
        const __nv_bfloat16* Al = As + (st * 2 + 1) * 128 * GK2;
        const __nv_bfloat16* Bh = Bs + (st * 2 + 0) * 128 * GK2;
        const __nv_bfloat16* Bl = Bs + (st * 2 + 1) * 128 * GK2;

#pragma unroll
        for (int kk = 0; kk < 32; kk += 16) {
            uint32_t ah[4][4], al[4][4], bh[4][2], bl[4][2];
#pragma unroll
            for (int i = 0; i < 4; i++) {
                int r = rA + i * 16 + g, c = kk + tig * 2;
                ah[i][0] = *(const uint32_t*)&Ah[r * GK2 + c];
                ah[i][1] = *(const uint32_t*)&Ah[(r + 8) * GK2 + c];
                ah[i][2] = *(const uint32_t*)&Ah[r * GK2 + c + 8];
                ah[i][3] = *(const uint32_t*)&Ah[(r + 8) * GK2 + c + 8];
                al[i][0] = *(const uint32_t*)&Al[r * GK2 + c];
                al[i][1] = *(const uint32_t*)&Al[(r + 8) * GK2 + c];
                al[i][2] = *(const uint32_t*)&Al[r * GK2 + c + 8];
                al[i][3] = *(const uint32_t*)&Al[(r + 8) * GK2 + c + 8];
            }
#pragma unroll
            for (int j = 0; j < 4; j++) {
                int n = cB + j * 8 + g, c = kk + tig * 2;
                bh[j][0] = *(const uint32_t*)&Bh[n * GK2 + c];
                bh[j][1] = *(const uint32_t*)&Bh[n * GK2 + c + 8];
                bl[j][0] = *(const uint32_t*)&Bl[n * GK2 + c];
                bl[j][1] = *(const uint32_t*)&Bl[n * GK2 + c + 8];
            }
#pragma unroll
            for (int i = 0; i < 4; i++)
#pragma unroll
                for (int j = 0; j < 4; j++) {
                    mma16816(acc[i][j], ah[i], bh[j]);
                    mma16816(acc[i][j], ah[i], bl[j]);
                    mma16816(acc[i][j], al[i], bh[j]);
                }
        }
        __syncthreads();
    }

    auto epi2 = [&](long row, int col, float v0, float v1) {
        v0 += bias[col]; v1 += bias[col + 1];
        if (EPI == 0) {
            out[row * (long)ldc + col]     = v0;
            out[row * (long)ldc + col + 1] = v1;
        } else if (EPI == 1) {
            float s0 = 1.f / (1.f + __expf(-v0));
            float s1 = 1.f / (1.f + __expf(-v1));
            if (col < 1024) {
                out[row * 1024 + col]     = s0;
                out[row * 1024 + col + 1] = s1;
            } else {
                int d = col - 1024;
                float rx0 = s0 * X[row * 1024 + d];
                float rx1 = s1 * X[row * 1024 + d + 1];
                __nv_bfloat16 h0 = __float2bfloat16(rx0);
                __nv_bfloat16 h1 = __float2bfloat16(rx1);
                __nv_bfloat162 hp; hp.x = h0; hp.y = h1;
                __nv_bfloat162 lp;
                lp.x = __float2bfloat16(rx0 - __bfloat162float(h0));
                lp.y = __float2bfloat16(rx1 - __bfloat162float(h1));
                *(__nv_bfloat162*)&g_RX_hi[row * 1024 + d] = hp;
                *(__nv_bfloat162*)&g_RX_lo[row * 1024 + d] = lp;
            }
        } else {
            float hc0 = tanhf(v0), hc1 = tanhf(v1);
            float x0 = X[row * 1024 + col], x1 = X[row * 1024 + col + 1];
            out[row * 1024 + col]     = x0 + UD[row * 1024 + col] * (hc0 - x0);
            out[row * 1024 + col + 1] = x1 + UD[row * 1024 + col + 1] * (hc1 - x1);
        }
    };

#pragma unroll
    for (int i = 0; i < 4; i++) {
        long r = row0 + rA + i * 16 + g;
#pragma unroll
        for (int j = 0; j < 4; j++) {
            int cc = col0 + cB + j * 8 + tig * 2;
            epi2(r,     cc, acc[i][j][0], acc[i][j][1]);
            epi2(r + 8, cc, acc[i][j][2], acc[i][j][3]);
        }
    }
}

// ---------------- scan init --------------------------------------------------
__global__ void scan_init(const float* __restrict__ prev_ht)
{
    int i = blockIdx.x * 256 + threadIdx.x;   // 32768
    if (i == 0) { g_cntA = 0; g_cntB = 0; }
    float v = prev_ht[i];
    g_hcur[i] = v;
    __nv_bfloat16 hi = __float2bfloat16(v);
    g_h_hi[i] = hi;
    g_h_lo[i] = __float2bfloat16(v - __bfloat162float(hi));
}

// ---------------- persistent scan: specialized producer/consumer blocks ------
// Blocks 0..63  : phase1 — 32 gate cols each (bx<32 -> u-gate, else r-gate->RH)
// Blocks 64..95 : phase2 — 32 candidate cols each; h kept in registers.
// Sync: phase1 release-adds cntA (phase2 waits); phase2 release-adds cntB.
extern __shared__ __align__(16) char dsraw[];
__global__ void __launch_bounds__(256, 1)
scan_persistent()
{
    __nv_bfloat16* wsh  = (__nv_bfloat16*)dsraw;          // 32 x WSP
    __nv_bfloat16* wsl  = wsh + 32 * WSP;
    __nv_bfloat16* hsh0 = wsl + 32 * WSP;                 // 32 x HSP2 (x2 bufs)
    __nv_bfloat16* hsl0 = hsh0 + 32 * HSP2;
    __nv_bfloat16* hsh1 = hsl0 + 32 * HSP2;
    __nv_bfloat16* hsl1 = hsh1 + 32 * HSP2;
    float* red = (float*)(hsl1 + 32 * HSP2);              // 8 x 1024 floats

    const int tid = threadIdx.x, bx = blockIdx.x;
    const int lane = tid & 31, warp = tid >> 5;
    const int g = lane >> 2, tig = lane & 3;
    const bool p1 = (bx < NB1);

    // output mapping: 32 rows x 32 cols, 4 cols/thread
    const int row = tid >> 3, c4 = (tid & 7) * 4;
    // staging mapping: 2 x uint4 per plane per thread
    const int sr0 = tid >> 4, sr1 = (tid + 256) >> 4;
    const int sq = (tid & 15) * 8;

    // ---- load this block's 32-col weight slice (once) ----
    {
        const int wc0 = p1 ? (bx * 32) : (2048 + (bx - NB1) * 32);
#pragma unroll
        for (int s = 0; s < 16; s++) {
            int f = tid + s * 256;                 // 0..4095
            int c = f >> 7, q = (f & 127) * 8;
            *(uint4*)(wsh + c * WSP + q) =
                *(const uint4*)&g_Wt_hi[(long)(wc0 + c) * 2048 + 1024 + q];
            *(uint4*)(wsl + c * WSP + q) =
                *(const uint4*)&g_Wt_lo[(long)(wc0 + c) * 2048 + 1024 + q];
        }
    }
    __syncthreads();

    auto ISSUE = [&](const __nv_bfloat16* srcH, const __nv_bfloat16* srcL,
                     int ch, int buf) {
        __nv_bfloat16* dh = buf ? hsh1 : hsh0;
        __nv_bfloat16* dl = buf ? hsl1 : hsl0;
        int kc = ch * 128;
        cpa16(dh + sr0 * HSP2 + sq, srcH + sr0 * 1024 + kc + sq);
        cpa16(dh + sr1 * HSP2 + sq, srcH + sr1 * 1024 + kc + sq);
        cpa16(dl + sr0 * HSP2 + sq, srcL + sr0 * 1024 + kc + sq);
        cpa16(dl + sr1 * HSP2 + sq, srcL + sr1 * 1024 + kc + sq);
        CPA_COMMIT;
    };

    // chunked MMA over staged activations vs smem weights -> red + sum
    auto GEMM32 = [&](const __nv_bfloat16* srcH, const __nv_bfloat16* srcL,
                      float4& sum) {
        float acc[2][4][4];
#pragma unroll
        for (int i = 0; i < 2; i++)
#pragma unroll
            for (int j = 0; j < 4; j++)
#pragma unroll
                for (int e = 0; e < 4; e++) acc[i][j][e] = 0.f;

        ISSUE(srcH, srcL, 0, 0);
        for (int ch = 0; ch < 8; ch++) {
            if (ch < 7) { ISSUE(srcH, srcL, ch + 1, (ch + 1) & 1); CPA_WAIT(1); }
            else        { CPA_WAIT(0); }
            __syncthreads();
            const __nv_bfloat16* Ah = (ch & 1) ? hsh1 : hsh0;
            const __nv_bfloat16* Al = (ch & 1) ? hsl1 : hsl0;
            const int kl = warp * 16 + tig * 2;        // chunk-local k
            const int kg = ch * 128 + kl;              // global k
            uint32_t ah[2][4], al[2][4], bh[4][2], bl[4][2];
#pragma unroll
            for (int i = 0; i < 2; i++) {
                int r = i * 16 + g;
                ah[i][0] = *(const uint32_t*)&Ah[r * HSP2 + kl];
                ah[i][1] = *(const uint32_t*)&Ah[(r + 8) * HSP2 + kl];
                ah[i][2] = *(const uint32_t*)&Ah[r * HSP2 + kl + 8];
                ah[i][3] = *(const uint32_t*)&Ah[(r + 8) * HSP2 + kl + 8];
                al[i][0] = *(const uint32_t*)&Al[r * HSP2 + kl];
                al[i][1] = *(const uint32_t*)&Al[(r + 8) * HSP2 + kl];
                al[i][2] = *(const uint32_t*)&Al[r * HSP2 + kl + 8];
                al[i][3] = *(const uint32_t*)&Al[(r + 8) * HSP2 + kl + 8];
            }
#pragma unroll
            for (int j = 0; j < 4; j++) {
                int n = j * 8 + g;
                bh[j][0] = *(const uint32_t*)&wsh[n * WSP + kg];
                bh[j][1] = *(const uint32_t*)&wsh[n * WSP + kg + 8];
                bl[j][0] = *(const uint32_t*)&wsl[n * WSP + kg];
                bl[j][1] = *(const uint32_t*)&wsl[n * WSP + kg + 8];
            }
#pragma unroll
            for (int i = 0; i < 2; i++)
#pragma unroll
                for (int j = 0; j < 4; j++) {
                    mma16816(acc[i][j], ah[i], bh[j]);
                    mma16816(acc[i][j], ah[i], bl[j]);
                    mma16816(acc[i][j], al[i], bh[j]);
                }
            __syncthreads();
        }
        // reduce 8 warps
#pragma unroll
        for (int i = 0; i < 2; i++)
#pragma unroll
            for (int j = 0; j < 4; j++) {
                int r = i * 16 + g, c = j * 8 + tig * 2;
                red[warp * 1024 + r * 32 + c]           = acc[i][j][0];
                red[warp * 1024 + r * 32 + c + 1]       = acc[i][j][1];
                red[warp * 1024 + (r + 8) * 32 + c]     = acc[i][j][2];
                red[warp * 1024 + (r + 8) * 32 + c + 1] = acc[i][j][3];
            }
        __syncthreads();
        sum = make_float4(0.f, 0.f, 0.f, 0.f);
#pragma unroll
        for (int w = 0; w < 8; w++) {
            float4 p = *(const float4*)&red[w * 1024 + row * 32 + c4];
            sum.x += p.x; sum.y += p.y; sum.z += p.z; sum.w += p.w;
        }
        __syncthreads();   // red reusable next call
    };

    if (p1) {
        // ======================= phase-1 blocks =======================
        const int gcol = bx * 32;          // gate col base (0..2047)
        const bool isU = (bx < 32);
        for (int t = 0; t < TT; t++) {
            float4 gv = *(const float4*)&g_gates[((long)row * TT + t) * 3072 + gcol + c4];
            if (t > 0) {                   // wait for phase2 step t-1
                if (tid == 0) while (acq_ld(&g_cntB) < (unsigned)(NB2 * t)) { }
                __syncthreads();
            }
            float4 hv = make_float4(0.f, 0.f, 0.f, 0.f);
            if (!isU)
                hv = __ldcg((const float4*)&g_hcur[row * 1024 + (gcol - 1024) + c4]);

            float4 s4;
            GEMM32(g_h_hi, g_h_lo, s4);

            float v0 = gv.x + s4.x, v1 = gv.y + s4.y;
            float v2 = gv.z + s4.z, v3 = gv.w + s4.w;
            float s0 = 1.f / (1.f + __expf(-v0));
            float s1 = 1.f / (1.f + __expf(-v1));
            float s2 = 1.f / (1.f + __expf(-v2));
            float s3 = 1.f / (1.f + __expf(-v3));
            if (isU) {
                *(float4*)&g_U[row * 1024 + gcol + c4] = make_float4(s0, s1, s2, s3);
            } else {
                int d = (gcol - 1024) + c4;
                float r0 = s0 * hv.x, r1 = s1 * hv.y, r2 = s2 * hv.z, r3 = s3 * hv.w;
                __align__(8) __nv_bfloat16 hb[4], lb[4];
                float rv[4] = {r0, r1, r2, r3};
#pragma unroll
                for (int e = 0; e < 4; e++) {
                    __nv_bfloat16 h = __float2bfloat16(rv[e]);
                    hb[e] = h;
                    lb[e] = __float2bfloat16(rv[e] - __bfloat162float(h));
                }
                *(uint2*)&g_rh_hi[row * 1024 + d] = *(uint2*)hb;
                *(uint2*)&g_rh_lo[row * 1024 + d] = *(uint2*)lb;
            }
            __syncthreads();
            if (tid == 0) rel_add(&g_cntA);
        }
    } else {
        // ======================= phase-2 blocks =======================
        const int d0 = (bx - NB1) * 32;
        // own h columns live in registers across steps
        float4 hreg = __ldcg((const float4*)&g_hcur[row * 1024 + d0 + c4]);
        for (int t = 0; t < TT; t++) {
            float4 gv = *(const float4*)&g_gates[((long)row * TT + t) * 3072 + 2048 + d0 + c4];
            if (tid == 0) while (acq_ld(&g_cntA) < (unsigned)(NB1 * (t + 1))) { }
            __syncthreads();
            float4 uu = __ldcg((const float4*)&g_U[row * 1024 + d0 + c4]);

            float4 s4;
            GEMM32(g_rh_hi, g_rh_lo, s4);

            float hc0 = tanhf(gv.x + s4.x);
            float hc1 = tanhf(gv.y + s4.y);
            float hc2 = tanhf(gv.z + s4.z);
            float hc3 = tanhf(gv.w + s4.w);
            float hn0 = hreg.x + uu.x * (hc0 - hreg.x);
            float hn1 = hreg.y + uu.y * (hc1 - hreg.y);
            float hn2 = hreg.z + uu.z * (hc2 - hreg.z);
            float hn3 = hreg.w + uu.w * (hc3 - hreg.w);
            hreg = make_float4(hn0, hn1, hn2, hn3);

            *(float4*)&g_hcur[row * 1024 + d0 + c4] = hreg;
            __align__(8) __nv_bfloat16 hb[4], lb[4];
            float hv[4] = {hn0, hn1, hn2, hn3};
#pragma unroll
            for (int e = 0; e < 4; e++) {
                __nv_bfloat16 h = __float2bfloat16(hv[e]);
                hb[e] = h;
                lb[e] = __float2bfloat16(hv[e] - __bfloat162float(h));
            }
            *(uint2*)&g_h_hi[row * 1024 + d0 + c4] = *(uint2*)hb;
            *(uint2*)&g_h_lo[row * 1024 + d0 + c4] = *(uint2*)lb;
            long ho = ((long)row * TT + t) * 1024 + d0 + c4;
            *(uint2*)&g_HT_hi[ho] = *(uint2*)hb;
            *(uint2*)&g_HT_lo[ho] = *(uint2*)lb;

            __syncthreads();
            if (tid == 0) rel_add(&g_cntB);
        }
    }
}

__global__ void copy_last(float* __restrict__ out)
{
    int i = blockIdx.x * 256 + threadIdx.x;   // 32768
    out[i] = g_hcur[i];
}

// ---------------- launch ------------------------------------------------------
#define SCAN_SMEM ((2*32*WSP + 4*32*HSP2) * 2 + 8*1024*4)
#define GEMM_SMEM (2 * 2 * 2 * 128 * GK2 * 2)

extern "C" void kernel_launch(void* const* d_in, const int* in_sizes, int n_in,
                              void* d_out, int out_size)
{
    const float* x       = (const float*)d_in[0];
    const float* prev_ht = (const float*)d_in[1];
    const float* weight  = (const float*)d_in[2];
    const float* bias    = (const float*)d_in[3];
    float* out = (float*)d_out;

    float *G, *UD;
    __nv_bfloat16 *Wth, *Wtl, *Xh, *Xl, *HTh, *HTl, *RXh, *RXl;
    cudaGetSymbolAddress((void**)&G,   g_gates);
    cudaGetSymbolAddress((void**)&UD,  g_UD);
    cudaGetSymbolAddress((void**)&Wth, g_Wt_hi);
    cudaGetSymbolAddress((void**)&Wtl, g_Wt_lo);
    cudaGetSymbolAddress((void**)&Xh,  g_X_hi);
    cudaGetSymbolAddress((void**)&Xl,  g_X_lo);
    cudaGetSymbolAddress((void**)&HTh, g_HT_hi);
    cudaGetSymbolAddress((void**)&HTl, g_HT_lo);
    cudaGetSymbolAddress((void**)&RXh, g_RX_hi);
    cudaGetSymbolAddress((void**)&RXl, g_RX_lo);

    static int attr_set = 0;
    if (!attr_set) {
        cudaFuncSetAttribute(scan_persistent,
                             cudaFuncAttributeMaxDynamicSharedMemorySize, SCAN_SMEM);
        cudaFuncSetAttribute(mma_gemm<0>,
                             cudaFuncAttributeMaxDynamicSharedMemorySize, GEMM_SMEM);
        cudaFuncSetAttribute(mma_gemm<1>,
                             cudaFuncAttributeMaxDynamicSharedMemorySize, GEMM_SMEM);
        cudaFuncSetAttribute(mma_gemm<2>,
                             cudaFuncAttributeMaxDynamicSharedMemorySize, GEMM_SMEM);
        attr_set = 1;
    }

    // prep: split W (transposed) and x into bf16 hi/lo
    conv_w_kernel<<<dim3(2048 / 64, 6144 / 64), 256>>>(weight);
    conv_x_kernel<<<MROWS * DD / 8 / 256, 256>>>(x);

    // gates = x @ Wxt + bt
    mma_gemm<0><<<dim3(3072 / 128, MROWS / 128), 256, GEMM_SMEM>>>(
        Xh, Xl, Xh, Xl, Wth, Wtl, bias, nullptr, G, nullptr, 1024, 3072);

    // scan
    scan_init<<<128, 256>>>(prev_ht);
    scan_persistent<<<NB1 + NB2, 256, SCAN_SMEM>>>();

    // F1: sigmoid(bd[:2D] + [x|ht] @ W[:,3072:5120]) -> UD, RX
    mma_gemm<1><<<dim3(2048 / 128, MROWS / 128), 256, GEMM_SMEM>>>(
        Xh, Xl, HTh, HTl, Wth + (size_t)3072 * 2048, Wtl + (size_t)3072 * 2048,
        bias + 3072, x, UD, nullptr, 2048, 2048);

    // F2: tanh(bd[2D:] + [rd*x|ht] @ W[:,5120:6144]); out = x + ud*(hc-x)
    mma_gemm<2><<<dim3(1024 / 128, MROWS / 128), 256, GEMM_SMEM>>>(
        RXh, RXl, HTh, HTl, Wth + (size_t)5120 * 2048, Wtl + (size_t)5120 * 2048,
        bias + 5120, x, out, UD, 2048, 1024);

    // last_ht
    copy_last<<<128, 256>>>(out + (size_t)MROWS * 1024);
}

// round 9
// speedup vs baseline: 1.1898x; 1.1898x over previous
#include <cuda_runtime.h>
#include <cuda_bf16.h>
#include <math.h>
#include <stdint.h>

// GridGRU: N=32, T=512, D=1024, H=1024
// inputs: x (N,T,D), prev_ht (N,H), weight (2048,6144), bias (6144)
// outputs: h (N,T,D) then last_ht (N,H), concatenated in d_out.

#define NN 32
#define TT 512
#define DD 1024
#define HH 1024
#define MROWS (NN*TT)        // 16384
#define WLD 6144
#define NB 128               // persistent scan blocks
#define GK2 40               // gemm smem k stride (bf16)
#define WSP 1032             // scan weight smem k stride
#define HSP 264              // scan activation smem k stride

// ---------------- scratch (device globals) -----------------------------------
__device__ float g_gates[(size_t)MROWS * 3072];        // 192 MB
__device__ float g_hcur[NN * HH];
__device__ float g_U[NN * HH];
__device__ float g_UD[(size_t)MROWS * DD];             // 64 MB
__device__ __nv_bfloat16 g_Wt_hi[(size_t)6144 * 2048]; // transposed [col][k]
__device__ __nv_bfloat16 g_Wt_lo[(size_t)6144 * 2048];
__device__ __nv_bfloat16 g_X_hi[(size_t)MROWS * DD], g_X_lo[(size_t)MROWS * DD];
__device__ __nv_bfloat16 g_HT_hi[(size_t)MROWS * HH], g_HT_lo[(size_t)MROWS * HH];
__device__ __nv_bfloat16 g_RX_hi[(size_t)MROWS * DD], g_RX_lo[(size_t)MROWS * DD];
__device__ __nv_bfloat16 g_h_hi[NN * HH], g_h_lo[NN * HH];
__device__ __nv_bfloat16 g_rh_hi[NN * HH], g_rh_lo[NN * HH];
__device__ unsigned g_barcnt;

__device__ __forceinline__ void mma16816(float* c, const uint32_t* a, const uint32_t* b)
{
    asm volatile(
        "mma.sync.aligned.m16n8k16.row.col.f32.bf16.bf16.f32 "
        "{%0,%1,%2,%3}, {%4,%5,%6,%7}, {%8,%9}, {%0,%1,%2,%3};\n"
        : "+f"(c[0]), "+f"(c[1]), "+f"(c[2]), "+f"(c[3])
        : "r"(a[0]), "r"(a[1]), "r"(a[2]), "r"(a[3]), "r"(b[0]), "r"(b[1]));
}

__device__ __forceinline__ void cpa16(void* smem, const void* g)
{
    uint32_t a = (uint32_t)__cvta_generic_to_shared(smem);
    asm volatile("cp.async.cg.shared.global [%0], [%1], 16;" :: "r"(a), "l"(g));
}
#define CPA_COMMIT asm volatile("cp.async.commit_group;" ::: "memory")
#define CPA_WAIT(n) asm volatile("cp.async.wait_group %0;" :: "n"(n) : "memory")

// ---------------- prep: split x to bf16 hi/lo --------------------------------
__global__ void conv_x_kernel(const float* __restrict__ x)
{
    long i = ((long)blockIdx.x * 256 + threadIdx.x) * 8;
    float4 v0 = *(const float4*)(x + i);
    float4 v1 = *(const float4*)(x + i + 4);
    float v[8] = {v0.x, v0.y, v0.z, v0.w, v1.x, v1.y, v1.z, v1.w};
    __align__(16) __nv_bfloat16 hb[8], lb[8];
#pragma unroll
    for (int e = 0; e < 8; e++) {
        __nv_bfloat16 h = __float2bfloat16(v[e]);
        hb[e] = h;
        lb[e] = __float2bfloat16(v[e] - __bfloat162float(h));
    }
    *(uint4*)&g_X_hi[i] = *(uint4*)hb;
    *(uint4*)&g_X_lo[i] = *(uint4*)lb;
}

// ---------------- prep: split + transpose weight to [col][k] bf16 ------------
__global__ void conv_w_kernel(const float* __restrict__ W)
{
    __shared__ float ws[64][65];
    const int k0 = blockIdx.x * 64, c0 = blockIdx.y * 64;
    const int tid = threadIdx.x;
#pragma unroll
    for (int s = 0; s < 4; s++) {
        int f = tid + s * 256;
        int kr = f >> 4, cc = (f & 15) * 4;
        float4 v = *(const float4*)(W + (long)(k0 + kr) * WLD + c0 + cc);
        ws[kr][cc] = v.x; ws[kr][cc + 1] = v.y; ws[kr][cc + 2] = v.z; ws[kr][cc + 3] = v.w;
    }
    __syncthreads();
    const int col = tid & 63, kq = tid >> 6;
    __align__(16) __nv_bfloat16 hb[16], lb[16];
#pragma unroll
    for (int j = 0; j < 16; j++) {
        float v = ws[kq * 16 + j][col];
        __nv_bfloat16 h = __float2bfloat16(v);
        hb[j] = h;
        lb[j] = __float2bfloat16(v - __bfloat162float(h));
    }
    long dst = (long)(c0 + col) * 2048 + k0 + kq * 16;
    ((uint4*)&g_Wt_hi[dst])[0] = ((uint4*)hb)[0];
    ((uint4*)&g_Wt_hi[dst])[1] = ((uint4*)hb)[1];
    ((uint4*)&g_Wt_lo[dst])[0] = ((uint4*)lb)[0];
    ((uint4*)&g_Wt_lo[dst])[1] = ((uint4*)lb)[1];
}

// ---------------- big GEMM: bf16 hi/lo, cp.async double-buffer ---------------
template<int EPI>
__global__ void __launch_bounds__(256, 2)
mma_gemm(const __nv_bfloat16* __restrict__ A0h, const __nv_bfloat16* __restrict__ A0l,
         const __nv_bfloat16* __restrict__ A1h, const __nv_bfloat16* __restrict__ A1l,
         const __nv_bfloat16* __restrict__ Bth, const __nv_bfloat16* __restrict__ Btl,
         const float* __restrict__ bias, const float* __restrict__ X,
         float* __restrict__ out, const float* __restrict__ UD,
         int K, int ldc)
{
    extern __shared__ __align__(16) char gsm[];
    __nv_bfloat16* As = (__nv_bfloat16*)gsm;        // [stage][hi/lo][128*GK2]
    __nv_bfloat16* Bs = As + 2 * 2 * 128 * GK2;

    const int tid = threadIdx.x, lane = tid & 31, warp = tid >> 5;
    const int warpM = warp & 1, warpN = warp >> 1;
    const int g = lane >> 2, tig = lane & 3;
    const int row0 = blockIdx.y * 128, col0 = blockIdx.x * 128;
    const int rA = warpM * 64, cB = warpN * 32;
    const int r0 = tid >> 2, kq = (tid & 3) * 8;
    const int r1 = r0 + 64;

    float acc[4][4][4];
#pragma unroll
    for (int i = 0; i < 4; i++)
#pragma unroll
        for (int j = 0; j < 4; j++)
#pragma unroll
            for (int e = 0; e < 4; e++) acc[i][j][e] = 0.f;

    auto ISSUE = [&](int k0, int st) {
        const __nv_bfloat16 *ph, *pl; int kb;
        if (k0 < 1024) { ph = A0h; pl = A0l; kb = k0; }
        else           { ph = A1h; pl = A1l; kb = k0 - 1024; }
        __nv_bfloat16* Ah = As + (st * 2 + 0) * 128 * GK2;
        __nv_bfloat16* Al = As + (st * 2 + 1) * 128 * GK2;
        __nv_bfloat16* Bh = Bs + (st * 2 + 0) * 128 * GK2;
        __nv_bfloat16* Bl = Bs + (st * 2 + 1) * 128 * GK2;
        cpa16(Ah + r0 * GK2 + kq, ph + (long)(row0 + r0) * 1024 + kb + kq);
        cpa16(Ah + r1 * GK2 + kq, ph + (long)(row0 + r1) * 1024 + kb + kq);
        cpa16(Al + r0 * GK2 + kq, pl + (long)(row0 + r0) * 1024 + kb + kq);
        cpa16(Al + r1 * GK2 + kq, pl + (long)(row0 + r1) * 1024 + kb + kq);
        cpa16(Bh + r0 * GK2 + kq, Bth + (long)(col0 + r0) * 2048 + k0 + kq);
        cpa16(Bh + r1 * GK2 + kq, Bth + (long)(col0 + r1) * 2048 + k0 + kq);
        cpa16(Bl + r0 * GK2 + kq, Btl + (long)(col0 + r0) * 2048 + k0 + kq);
        cpa16(Bl + r1 * GK2 + kq, Btl + (long)(col0 + r1) * 2048 + k0 + kq);
    };

    const int KT = K / 32;
    ISSUE(0, 0); CPA_COMMIT;

    for (int kt = 0; kt < KT; kt++) {
        const int st = kt & 1;
        if (kt + 1 < KT) { ISSUE((kt + 1) * 32, st ^ 1); CPA_COMMIT; CPA_WAIT(1); }
        else             { CPA_WAIT(0); }
        __syncthreads();

        const __nv_bfloat16* Ah = As + (st * 2 + 0) * 128 * GK2;
        const __nv_bfloat16* Al = As + (st * 2 + 1) * 128 * GK2;
        const __nv_bfloat16* Bh = Bs + (st * 2 + 0) * 128 * GK2;
        const __nv_bfloat16* Bl = Bs + (st * 2 + 1) * 128 * GK2;

#pragma unroll
        for (int kk = 0; kk < 32; kk += 16) {
            uint32_t ah[4][4], al[4][4], bh[4][2], bl[4][2];
#pragma unroll
            for (int i = 0; i < 4; i++) {
                int r = rA + i * 16 + g, c = kk + tig * 2;
                ah[i][0] = *(const uint32_t*)&Ah[r * GK2 + c];
                ah[i][1] = *(const uint32_t*)&Ah[(r + 8) * GK2 + c];
                ah[i][2] = *(const uint32_t*)&Ah[r * GK2 + c + 8];
                ah[i][3] = *(const uint32_t*)&Ah[(r + 8) * GK2 + c + 8];
                al[i][0] = *(const uint32_t*)&Al[r * GK2 + c];
                al[i][1] = *(const uint32_t*)&Al[(r + 8) * GK2 + c];
                al[i][2] = *(const uint32_t*)&Al[r * GK2 + c + 8];
                al[i][3] = *(const uint32_t*)&Al[(r + 8) * GK2 + c + 8];
            }
#pragma unroll
            for (int j = 0; j < 4; j++) {
                int n = cB + j * 8 + g, c = kk + tig * 2;
                bh[j][0] = *(const uint32_t*)&Bh[n * GK2 + c];
                bh[j][1] = *(const uint32_t*)&Bh[n * GK2 + c + 8];
                bl[j][0] = *(const uint32_t*)&Bl[n * GK2 + c];
                bl[j][1] = *(const uint32_t*)&Bl[n * GK2 + c + 8];
            }
#pragma unroll
            for (int i = 0; i < 4; i++)
#pragma unroll
                for (int j = 0; j < 4; j++) {
                    mma16816(acc[i][j], ah[i], bh[j]);
                    mma16816(acc[i][j], ah[i], bl[j]);
                    mma16816(acc[i][j], al[i], bh[j]);
                }
        }
        __syncthreads();
    }

    auto epi2 = [&](long row, int col, float v0, float v1) {
        v0 += bias[col]; v1 += bias[col + 1];
        if (EPI == 0) {
            out[row * (long)ldc + col]     = v0;
            out[row * (long)ldc + col + 1] = v1;
        } else if (EPI == 1) {
            float s0 = 1.f / (1.f + __expf(-v0));
            float s1 = 1.f / (1.f + __expf(-v1));
            if (col < 1024) {
                out[row * 1024 + col]     = s0;
                out[row * 1024 + col + 1] = s1;
            } else {
                int d = col - 1024;
                float rx0 = s0 * X[row * 1024 + d];
                float rx1 = s1 * X[row * 1024 + d + 1];
                __nv_bfloat16 h0 = __float2bfloat16(rx0);
                __nv_bfloat16 h1 = __float2bfloat16(rx1);
                __nv_bfloat162 hp; hp.x = h0; hp.y = h1;
                __nv_bfloat162 lp;
                lp.x = __float2bfloat16(rx0 - __bfloat162float(h0));
                lp.y = __float2bfloat16(rx1 - __bfloat162float(h1));
                *(__nv_bfloat162*)&g_RX_hi[row * 1024 + d] = hp;
                *(__nv_bfloat162*)&g_RX_lo[row * 1024 + d] = lp;
            }
        } else {
            float hc0 = tanhf(v0), hc1 = tanhf(v1);
            float x0 = X[row * 1024 + col], x1 = X[row * 1024 + col + 1];
            out[row * 1024 + col]     = x0 + UD[row * 1024 + col] * (hc0 - x0);
            out[row * 1024 + col + 1] = x1 + UD[row * 1024 + col + 1] * (hc1 - x1);
        }
    };

#pragma unroll
    for (int i = 0; i < 4; i++) {
        long r = row0 + rA + i * 16 + g;
#pragma unroll
        for (int j = 0; j < 4; j++) {
            int cc = col0 + cB + j * 8 + tig * 2;
            epi2(r,     cc, acc[i][j][0], acc[i][j][1]);
            epi2(r + 8, cc, acc[i][j][2], acc[i][j][3]);
        }
    }
}

// ---------------- scan init --------------------------------------------------
__global__ void scan_init(const float* __restrict__ prev_ht)
{
    int i = blockIdx.x * 256 + threadIdx.x;   // 32768
    if (i == 0) g_barcnt = 0;
    float v = prev_ht[i];
    g_hcur[i] = v;
    __nv_bfloat16 hi = __float2bfloat16(v);
    g_h_hi[i] = hi;
    g_h_lo[i] = __float2bfloat16(v - __bfloat162float(hi));
}

__device__ __forceinline__ void gridbar(unsigned target)
{
    __syncthreads();
    if (threadIdx.x == 0) {
        asm volatile("red.release.gpu.global.add.u32 [%0], 1;"
                     :: "l"(&g_barcnt) : "memory");
        unsigned v;
        do {
            asm volatile("ld.acquire.gpu.global.u32 %0, [%1];"
                         : "=r"(v) : "l"(&g_barcnt) : "memory");
        } while (v < target);
    }
    __syncthreads();
}

// ---------------- persistent tensor-core scan (3-buffer cp.async ring) -------
// 128 blocks x 256 threads. Block bx owns 16 gate cols (phase1; bx<64 -> U,
// else RH) and 8 candidate cols (phase2). Weights persist in smem; activations
// staged per step in 4 chunks of 256k through a 3-buffer ring with ONE
// __syncthreads per chunk (WAIT -> sync -> ISSUE(ch+2) -> MMA(ch); buffer b is
// rewritten by ISSUE(b+3) only after SYNC(b+1), which dominates all MMA(b)).
extern __shared__ __align__(16) char dsraw[];
__global__ void __launch_bounds__(256, 1)
scan_persistent()
{
    __nv_bfloat16* ws1h = (__nv_bfloat16*)dsraw;
    __nv_bfloat16* ws1l = ws1h + 16 * WSP;
    __nv_bfloat16* ws2h = ws1l + 16 * WSP;
    __nv_bfloat16* ws2l = ws2h + 8 * WSP;
    __nv_bfloat16* hbuf = ws2l + 8 * WSP;       // 3 bufs x [hi|lo] x 32*HSP
    float* red = (float*)(hbuf + 3 * 2 * 32 * HSP);

    const int tid = threadIdx.x, bx = blockIdx.x;
    const int lane = tid & 31, warp = tid >> 5;
    const int g = lane >> 2, tig = lane & 3;

    // ---- weight slices from pre-split transposed W (once) ----
#pragma unroll
    for (int s = 0; s < 8; s++) {
        int f = tid + s * 256;                 // 0..2047
        int c = f >> 7, q = (f & 127) * 8;
        *(uint4*)(ws1h + c * WSP + q) = *(const uint4*)&g_Wt_hi[(long)(bx * 16 + c) * 2048 + 1024 + q];
        *(uint4*)(ws1l + c * WSP + q) = *(const uint4*)&g_Wt_lo[(long)(bx * 16 + c) * 2048 + 1024 + q];
    }
#pragma unroll
    for (int s = 0; s < 4; s++) {
        int f = tid + s * 256;                 // 0..1023
        int c = f >> 7, q = (f & 127) * 8;
        *(uint4*)(ws2h + c * WSP + q) = *(const uint4*)&g_Wt_hi[(long)(2048 + bx * 8 + c) * 2048 + 1024 + q];
        *(uint4*)(ws2l + c * WSP + q) = *(const uint4*)&g_Wt_lo[(long)(2048 + bx * 8 + c) * 2048 + 1024 + q];
    }
    __syncthreads();

    const int o1 = tid * 2;
    const int r1 = o1 >> 4, c1 = o1 & 15;
    const int col1 = bx * 16 + c1;
    const int r2 = tid >> 3, c2 = tid & 7;
    const int d2 = bx * 8 + c2;

    // staging map: id = tid + s*256 -> r = id>>5, q = (id&31)*8
    const int sr[4] = { tid >> 5, (tid + 256) >> 5, (tid + 512) >> 5, (tid + 768) >> 5 };
    const int sq = (tid & 31) * 8;

    auto BUF_H = [&](int b) { return hbuf + (b * 2 + 0) * 32 * HSP; };
    auto BUF_L = [&](int b) { return hbuf + (b * 2 + 1) * 32 * HSP; };

    auto ISSUE = [&](const __nv_bfloat16* srcH, const __nv_bfloat16* srcL,
                     int ch, int buf) {
        __nv_bfloat16* dh = BUF_H(buf);
        __nv_bfloat16* dl = BUF_L(buf);
        int kc = ch * 256;
#pragma unroll
        for (int s = 0; s < 4; s++) {
            int r = sr[s];
            cpa16(dh + r * HSP + sq, srcH + r * 1024 + kc + sq);
            cpa16(dl + r * HSP + sq, srcL + r * 1024 + kc + sq);
        }
        CPA_COMMIT;
    };

    unsigned tgt = NB;

    for (int t = 0; t < TT; t++) {
        // ---- phase-1 staging starts immediately (chunks 0,1 in flight) ----
        ISSUE(g_h_hi, g_h_lo, 0, 0);
        ISSUE(g_h_hi, g_h_lo, 1, 1);

        float2 g1 = *(const float2*)&g_gates[((long)r1 * TT + t) * 3072 + col1];
        float2 hv1 = make_float2(0.f, 0.f);
        if (col1 >= 1024)
            hv1 = __ldcg((const float2*)&g_hcur[r1 * 1024 + (col1 - 1024)]);
        float gg2 = g_gates[((long)r2 * TT + t) * 3072 + 2048 + d2];
        float hp = __ldcg(&g_hcur[r2 * 1024 + d2]);

        // ================= phase 1 =================
        float acc[2][2][4];
#pragma unroll
        for (int i = 0; i < 2; i++)
#pragma unroll
            for (int j = 0; j < 2; j++)
#pragma unroll
                for (int e = 0; e < 4; e++) acc[i][j][e] = 0.f;

#pragma unroll
        for (int ch = 0; ch < 4; ch++) {
            if (ch < 3) CPA_WAIT(1); else CPA_WAIT(0);
            __syncthreads();
            if (ch < 2) ISSUE(g_h_hi, g_h_lo, ch + 2, (ch + 2) % 3);
            const __nv_bfloat16* Ah = BUF_H(ch % 3);
            const __nv_bfloat16* Al = BUF_L(ch % 3);
#pragma unroll
            for (int kk = 0; kk < 32; kk += 16) {
                int kl = warp * 32 + kk + tig * 2;   // chunk-local
                int kg = ch * 256 + kl;              // global k
                uint32_t ah[2][4], al[2][4], bh[2][2], bl[2][2];
#pragma unroll
                for (int i = 0; i < 2; i++) {
                    int r = i * 16 + g;
                    ah[i][0] = *(const uint32_t*)&Ah[r * HSP + kl];
                    ah[i][1] = *(const uint32_t*)&Ah[(r + 8) * HSP + kl];
                    ah[i][2] = *(const uint32_t*)&Ah[r * HSP + kl + 8];
                    ah[i][3] = *(const uint32_t*)&Ah[(r + 8) * HSP + kl + 8];
                    al[i][0] = *(const uint32_t*)&Al[r * HSP + kl];
                    al[i][1] = *(const uint32_t*)&Al[(r + 8) * HSP + kl];
                    al[i][2] = *(const uint32_t*)&Al[r * HSP + kl + 8];
                    al[i][3] = *(const uint32_t*)&Al[(r + 8) * HSP + kl + 8];
                }
#pragma unroll
                for (int j = 0; j < 2; j++) {
                    int n = j * 8 + g;
                    bh[j][0] = *(const uint32_t*)&ws1h[n * WSP + kg];
                    bh[j][1] = *(const uint32_t*)&ws1h[n * WSP + kg + 8];
                    bl[j][0] = *(const uint32_t*)&ws1l[n * WSP + kg];
                    bl[j][1] = *(const uint32_t*)&ws1l[n * WSP + kg + 8];
                }
#pragma unroll
                for (int i = 0; i < 2; i++)
#pragma unroll
                    for (int j = 0; j < 2; j++) {
                        mma16816(acc[i][j], ah[i], bh[j]);
                        mma16816(acc[i][j], ah[i], bl[j]);
                        mma16816(acc[i][j], al[i], bh[j]);
                    }
            }
        }
        // red is per-warp private: no sync needed before the writes
#pragma unroll
        for (int i = 0; i < 2; i++)
#pragma unroll
            for (int j = 0; j < 2; j++) {
                int r = i * 16 + g, c = j * 8 + tig * 2;
                red[warp * 512 + r * 16 + c]           = acc[i][j][0];
                red[warp * 512 + r * 16 + c + 1]       = acc[i][j][1];
                red[warp * 512 + (r + 8) * 16 + c]     = acc[i][j][2];
                red[warp * 512 + (r + 8) * 16 + c + 1] = acc[i][j][3];
            }
        __syncthreads();
        {
            float v0 = g1.x, v1 = g1.y;
#pragma unroll
            for (int w = 0; w < 8; w++) {
                float2 p = *(const float2*)&red[w * 512 + o1];
                v0 += p.x; v1 += p.y;
            }
            float s0 = 1.f / (1.f + __expf(-v0));
            float s1 = 1.f / (1.f + __expf(-v1));
            if (col1 < 1024) {
                *(float2*)&g_U[r1 * 1024 + col1] = make_float2(s0, s1);
            } else {
                int d = col1 - 1024;
                float rh0 = s0 * hv1.x, rh1 = s1 * hv1.y;
                __nv_bfloat16 h0 = __float2bfloat16(rh0);
                __nv_bfloat16 h1 = __float2bfloat16(rh1);
                __nv_bfloat162 hip; hip.x = h0; hip.y = h1;
                __nv_bfloat162 lop;
                lop.x = __float2bfloat16(rh0 - __bfloat162float(h0));
                lop.y = __float2bfloat16(rh1 - __bfloat162float(h1));
                *(__nv_bfloat162*)&g_rh_hi[r1 * 1024 + d] = hip;
                *(__nv_bfloat162*)&g_rh_lo[r1 * 1024 + d] = lop;
            }
        }

        gridbar(tgt); tgt += NB;

        // ================= phase 2 =================
        ISSUE(g_rh_hi, g_rh_lo, 0, 0);
        ISSUE(g_rh_hi, g_rh_lo, 1, 1);
        float uu = __ldcg(&g_U[r2 * 1024 + d2]);

        float acc2[2][4];
#pragma unroll
        for (int i = 0; i < 2; i++)
#pragma unroll
            for (int e = 0; e < 4; e++) acc2[i][e] = 0.f;

#pragma unroll
        for (int ch = 0; ch < 4; ch++) {
            if (ch < 3) CPA_WAIT(1); else CPA_WAIT(0);
            __syncthreads();
            if (ch < 2) ISSUE(g_rh_hi, g_rh_lo, ch + 2, (ch + 2) % 3);
            const __nv_bfloat16* Ah = BUF_H(ch % 3);
            const __nv_bfloat16* Al = BUF_L(ch % 3);
#pragma unroll
            for (int kk = 0; kk < 32; kk += 16) {
                int kl = warp * 32 + kk + tig * 2;
                int kg = ch * 256 + kl;
                uint32_t ah[2][4], al[2][4], bh[2], bl[2];
#pragma unroll
                for (int i = 0; i < 2; i++) {
                    int r = i * 16 + g;
                    ah[i][0] = *(const uint32_t*)&Ah[r * HSP + kl];
                    ah[i][1] = *(const uint32_t*)&Ah[(r + 8) * HSP + kl];
                    ah[i][2] = *(const uint32_t*)&Ah[r * HSP + kl + 8];
                    ah[i][3] = *(const uint32_t*)&Ah[(r + 8) * HSP + kl + 8];
                    al[i][0] = *(const uint32_t*)&Al[r * HSP + kl];
                    al[i][1] = *(const uint32_t*)&Al[(r + 8) * HSP + kl];
                    al[i][2] = *(const uint32_t*)&Al[r * HSP + kl + 8];
                    al[i][3] = *(const uint32_t*)&Al[(r + 8) * HSP + kl + 8];
                }
                {
                    int n = g;
                    bh[0] = *(const uint32_t*)&ws2h[n * WSP + kg];
                    bh[1] = *(const uint32_t*)&ws2h[n * WSP + kg + 8];
                    bl[0] = *(const uint32_t*)&ws2l[n * WSP + kg];
                    bl[1] = *(const uint32_t*)&ws2l[n * WSP + kg + 8];
                }
#pragma unroll
                for (int i = 0; i < 2; i++) {
                    mma16816(acc2[i], ah[i], bh);
                    mma16816(acc2[i], ah[i], bl);
                    mma16816(acc2[i], al[i], bh);
                }
            }
        }
#pragma unroll
        for (int i = 0; i < 2; i++) {
            int r = i * 16 + g, c = tig * 2;
            red[warp * 256 + r * 8 + c]           = acc2[i][0];
            red[warp * 256 + r * 8 + c + 1]       = acc2[i][1];
            red[warp * 256 + (r + 8) * 8 + c]     = acc2[i][2];
            red[warp * 256 + (r + 8) * 8 + c + 1] = acc2[i][3];
        }
        __syncthreads();
        {
            float v = gg2;
#pragma unroll
            for (int w = 0; w < 8; w++) v += red[w * 256 + tid];
            float hc = tanhf(v);
            float hn = hp + uu * (hc - hp);
            g_hcur[r2 * 1024 + d2] = hn;
            __nv_bfloat16 hi = __float2bfloat16(hn);
            __nv_bfloat16 lo = __float2bfloat16(hn - __bfloat162float(hi));
            g_h_hi[r2 * 1024 + d2] = hi;
            g_h_lo[r2 * 1024 + d2] = lo;
            long ho = ((long)r2 * TT + t) * 1024 + d2;
            g_HT_hi[ho] = hi;
            g_HT_lo[ho] = lo;
        }

        gridbar(tgt); tgt += NB;
    }
}

__global__ void copy_last(float* __restrict__ out)
{
    int i = blockIdx.x * 256 + threadIdx.x;   // 32768
    out[i] = g_hcur[i];
}

// ---------------- launch ------------------------------------------------------
#define SCAN_SMEM ((48*WSP + 3*2*32*HSP) * 2 + 8*512*4)
#define GEMM_SMEM (2 * 2 * 2 * 128 * GK2 * 2)

extern "C" void kernel_launch(void* const* d_in, const int* in_sizes, int n_in,
                              void* d_out, int out_size)
{
    const float* x       = (const float*)d_in[0];
    const float* prev_ht = (const float*)d_in[1];
    const float* weight  = (const float*)d_in[2];
    const float* bias    = (const float*)d_in[3];
    float* out = (float*)d_out;

    float *G, *UD;
    __nv_bfloat16 *Wth, *Wtl, *Xh, *Xl, *HTh, *HTl, *RXh, *RXl;
    cudaGetSymbolAddress((void**)&G,   g_gates);
    cudaGetSymbolAddress((void**)&UD,  g_UD);
    cudaGetSymbolAddress((void**)&Wth, g_Wt_hi);
    cudaGetSymbolAddress((void**)&Wtl, g_Wt_lo);
    cudaGetSymbolAddress((void**)&Xh,  g_X_hi);
    cudaGetSymbolAddress((void**)&Xl,  g_X_lo);
    cudaGetSymbolAddress((void**)&HTh, g_HT_hi);
    cudaGetSymbolAddress((void**)&HTl, g_HT_lo);
    cudaGetSymbolAddress((void**)&RXh, g_RX_hi);
    cudaGetSymbolAddress((void**)&RXl, g_RX_lo);

    static int attr_set = 0;
    if (!attr_set) {
        cudaFuncSetAttribute(scan_persistent,
                             cudaFuncAttributeMaxDynamicSharedMemorySize, SCAN_SMEM);
        cudaFuncSetAttribute(mma_gemm<0>,
                             cudaFuncAttributeMaxDynamicSharedMemorySize, GEMM_SMEM);
        cudaFuncSetAttribute(mma_gemm<1>,
                             cudaFuncAttributeMaxDynamicSharedMemorySize, GEMM_SMEM);
        cudaFuncSetAttribute(mma_gemm<2>,
                             cudaFuncAttributeMaxDynamicSharedMemorySize, GEMM_SMEM);
        attr_set = 1;
    }

    // prep: split W (transposed) and x into bf16 hi/lo
    conv_w_kernel<<<dim3(2048 / 64, 6144 / 64), 256>>>(weight);
    conv_x_kernel<<<MROWS * DD / 8 / 256, 256>>>(x);

    // gates = x @ Wxt + bt
    mma_gemm<0><<<dim3(3072 / 128, MROWS / 128), 256, GEMM_SMEM>>>(
        Xh, Xl, Xh, Xl, Wth, Wtl, bias, nullptr, G, nullptr, 1024, 3072);

    // scan
    scan_init<<<128, 256>>>(prev_ht);
    scan_persistent<<<NB, 256, SCAN_SMEM>>>();

    // F1: sigmoid(bd[:2D] + [x|ht] @ W[:,3072:5120]) -> UD, RX
    mma_gemm<1><<<dim3(2048 / 128, MROWS / 128), 256, GEMM_SMEM>>>(
        Xh, Xl, HTh, HTl, Wth + (size_t)3072 * 2048, Wtl + (size_t)3072 * 2048,
        bias + 3072, x, UD, nullptr, 2048, 2048);

    // F2: tanh(bd[2D:] + [rd*x|ht] @ W[:,5120:6144]); out = x + ud*(hc-x)
    mma_gemm<2><<<dim3(1024 / 128, MROWS / 128), 256, GEMM_SMEM>>>(
        RXh, RXl, HTh, HTl, Wth + (size_t)5120 * 2048, Wtl + (size_t)5120 * 2048,
        bias + 5120, x, out, UD, 2048, 1024);

    // last_ht
    copy_last<<<128, 256>>>(out + (size_t)MROWS * 1024);
}

// round 12
// speedup vs baseline: 1.2311x; 1.0347x over previous
#include <cuda_runtime.h>
#include <cuda_bf16.h>
#include <math.h>
#include <stdint.h>

// GridGRU: N=32, T=512, D=1024, H=1024
// inputs: x (N,T,D), prev_ht (N,H), weight (2048,6144), bias (6144)
// outputs: h (N,T,D) then last_ht (N,H), concatenated in d_out.

#define NN 32
#define TT 512
#define DD 1024
#define HH 1024
#define MROWS (NN*TT)        // 16384
#define WLD 6144
#define NB 128               // persistent scan blocks
#define GK2 40               // gemm smem k stride (bf16); 80B rows (16B-multiple)
#define WSP 1032             // scan weight smem k stride
#define HSP 264              // scan activation smem k stride

// ---------------- scratch (device globals) -----------------------------------
__device__ float g_gates[(size_t)MROWS * 3072];        // 192 MB
__device__ float g_hcur[NN * HH];
__device__ float g_U[NN * HH];
__device__ float g_UD[(size_t)MROWS * DD];             // 64 MB
__device__ __nv_bfloat16 g_Wt_hi[(size_t)6144 * 2048]; // transposed [col][k]
__device__ __nv_bfloat16 g_Wt_lo[(size_t)6144 * 2048];
__device__ __nv_bfloat16 g_X_hi[(size_t)MROWS * DD], g_X_lo[(size_t)MROWS * DD];
__device__ __nv_bfloat16 g_HT_hi[(size_t)MROWS * HH], g_HT_lo[(size_t)MROWS * HH];
__device__ __nv_bfloat16 g_RX_hi[(size_t)MROWS * DD], g_RX_lo[(size_t)MROWS * DD];
__device__ __nv_bfloat16 g_h_hi[NN * HH], g_h_lo[NN * HH];
__device__ __nv_bfloat16 g_rh_hi[NN * HH], g_rh_lo[NN * HH];
__device__ unsigned g_barcnt;

__device__ __forceinline__ void mma16816(float* c, const uint32_t* a, const uint32_t* b)
{
    asm volatile(
        "mma.sync.aligned.m16n8k16.row.col.f32.bf16.bf16.f32 "
        "{%0,%1,%2,%3}, {%4,%5,%6,%7}, {%8,%9}, {%0,%1,%2,%3};\n"
        : "+f"(c[0]), "+f"(c[1]), "+f"(c[2]), "+f"(c[3])
        : "r"(a[0]), "r"(a[1]), "r"(a[2]), "r"(a[3]), "r"(b[0]), "r"(b[1]));
}

__device__ __forceinline__ void ldsm_x4(uint32_t* r, uint32_t saddr)
{
    asm volatile("ldmatrix.sync.aligned.m8n8.x4.shared.b16 {%0,%1,%2,%3}, [%4];\n"
                 : "=r"(r[0]), "=r"(r[1]), "=r"(r[2]), "=r"(r[3]) : "r"(saddr));
}

__device__ __forceinline__ void cpa16(void* smem, const void* g)
{
    uint32_t a = (uint32_t)__cvta_generic_to_shared(smem);
    asm volatile("cp.async.cg.shared.global [%0], [%1], 16;" :: "r"(a), "l"(g));
}
#define CPA_COMMIT asm volatile("cp.async.commit_group;" ::: "memory")
#define CPA_WAIT(n) asm volatile("cp.async.wait_group %0;" :: "n"(n) : "memory")

// ---------------- prep: split x to bf16 hi/lo --------------------------------
__global__ void conv_x_kernel(const float* __restrict__ x)
{
    long i = ((long)blockIdx.x * 256 + threadIdx.x) * 8;
    float4 v0 = *(const float4*)(x + i);
    float4 v1 = *(const float4*)(x + i + 4);
    float v[8] = {v0.x, v0.y, v0.z, v0.w, v1.x, v1.y, v1.z, v1.w};
    __align__(16) __nv_bfloat16 hb[8], lb[8];
#pragma unroll
    for (int e = 0; e < 8; e++) {
        __nv_bfloat16 h = __float2bfloat16(v[e]);
        hb[e] = h;
        lb[e] = __float2bfloat16(v[e] - __bfloat162float(h));
    }
    *(uint4*)&g_X_hi[i] = *(uint4*)hb;
    *(uint4*)&g_X_lo[i] = *(uint4*)lb;
}

// ---------------- prep: split + transpose weight to [col][k] bf16 ------------
__global__ void conv_w_kernel(const float* __restrict__ W)
{
    __shared__ float ws[64][65];
    const int k0 = blockIdx.x * 64, c0 = blockIdx.y * 64;
    const int tid = threadIdx.x;
#pragma unroll
    for (int s = 0; s < 4; s++) {
        int f = tid + s * 256;
        int kr = f >> 4, cc = (f & 15) * 4;
        float4 v = *(const float4*)(W + (long)(k0 + kr) * WLD + c0 + cc);
        ws[kr][cc] = v.x; ws[kr][cc + 1] = v.y; ws[kr][cc + 2] = v.z; ws[kr][cc + 3] = v.w;
    }
    __syncthreads();
    const int col = tid & 63, kq = tid >> 6;
    __align__(16) __nv_bfloat16 hb[16], lb[16];
#pragma unroll
    for (int j = 0; j < 16; j++) {
        float v = ws[kq * 16 + j][col];
        __nv_bfloat16 h = __float2bfloat16(v);
        hb[j] = h;
        lb[j] = __float2bfloat16(v - __bfloat162float(h));
    }
    long dst = (long)(c0 + col) * 2048 + k0 + kq * 16;
    ((uint4*)&g_Wt_hi[dst])[0] = ((uint4*)hb)[0];
    ((uint4*)&g_Wt_hi[dst])[1] = ((uint4*)hb)[1];
    ((uint4*)&g_Wt_lo[dst])[0] = ((uint4*)lb)[0];
    ((uint4*)&g_Wt_lo[dst])[1] = ((uint4*)lb)[1];
}

// ---------------- big GEMM: bf16 hi/lo, cp.async + ldmatrix ------------------
template<int EPI>
__global__ void __launch_bounds__(256, 2)
mma_gemm(const __nv_bfloat16* __restrict__ A0h, const __nv_bfloat16* __restrict__ A0l,
         const __nv_bfloat16* __restrict__ A1h, const __nv_bfloat16* __restrict__ A1l,
         const __nv_bfloat16* __restrict__ Bth, const __nv_bfloat16* __restrict__ Btl,
         const float* __restrict__ bias, const float* __restrict__ X,
         float* __restrict__ out, const float* __restrict__ UD,
         int K, int ldc)
{
    extern __shared__ __align__(16) char gsm[];
    __nv_bfloat16* As = (__nv_bfloat16*)gsm;        // [stage][hi/lo][128*GK2]
    __nv_bfloat16* Bs = As + 2 * 2 * 128 * GK2;
    const uint32_t s0s = (uint32_t)__cvta_generic_to_shared(gsm);
    const uint32_t PLANE = 128 * GK2 * 2;           // bytes per plane

    const int tid = threadIdx.x, lane = tid & 31, warp = tid >> 5;
    const int warpM = warp & 1, warpN = warp >> 1;
    const int g = lane >> 2, tig = lane & 3;
    const int row0 = blockIdx.y * 128, col0 = blockIdx.x * 128;
    const int rA = warpM * 64, cB = warpN * 32;
    const int r0 = tid >> 2, kq = (tid & 3) * 8;
    const int r1 = r0 + 64;

    // ldmatrix lane address components (aligned: 40 bf16 = 80 B = 5*16 B rows)
    const int arow = ((lane >> 3) & 1) * 8 + (lane & 7);
    const int acol = (lane >> 4) * 8;
    const int brow = (lane >> 4) * 8 + (lane & 7);
    const int bcol = ((lane >> 3) & 1) * 8;

    float acc[4][4][4];
#pragma unroll
    for (int i = 0; i < 4; i++)
#pragma unroll
        for (int j = 0; j < 4; j++)
#pragma unroll
            for (int e = 0; e < 4; e++) acc[i][j][e] = 0.f;

    auto ISSUE = [&](int k0, int st) {
        const __nv_bfloat16 *ph, *pl; int kb;
        if (k0 < 1024) { ph = A0h; pl = A0l; kb = k0; }
        else           { ph = A1h; pl = A1l; kb = k0 - 1024; }
        __nv_bfloat16* Ah = As + (st * 2 + 0) * 128 * GK2;
        __nv_bfloat16* Al = As + (st * 2 + 1) * 128 * GK2;
        __nv_bfloat16* Bh = Bs + (st * 2 + 0) * 128 * GK2;
        __nv_bfloat16* Bl = Bs + (st * 2 + 1) * 128 * GK2;
        cpa16(Ah + r0 * GK2 + kq, ph + (long)(row0 + r0) * 1024 + kb + kq);
        cpa16(Ah + r1 * GK2 + kq, ph + (long)(row0 + r1) * 1024 + kb + kq);
        cpa16(Al + r0 * GK2 + kq, pl + (long)(row0 + r0) * 1024 + kb + kq);
        cpa16(Al + r1 * GK2 + kq, pl + (long)(row0 + r1) * 1024 + kb + kq);
        cpa16(Bh + r0 * GK2 + kq, Bth + (long)(col0 + r0) * 2048 + k0 + kq);
        cpa16(Bh + r1 * GK2 + kq, Bth + (long)(col0 + r1) * 2048 + k0 + kq);
        cpa16(Bl + r0 * GK2 + kq, Btl + (long)(col0 + r0) * 2048 + k0 + kq);
        cpa16(Bl + r1 * GK2 + kq, Btl + (long)(col0 + r1) * 2048 + k0 + kq);
    };

    const int KT = K / 32;
    ISSUE(0, 0); CPA_COMMIT;

    for (int kt = 0; kt < KT; kt++) {
        const int st = kt & 1;
        if (kt + 1 < KT) { ISSUE((kt + 1) * 32, st ^ 1); CPA_COMMIT; CPA_WAIT(1); }
        else             { CPA_WAIT(0); }
        __syncthreads();

        const uint32_t sAh = s0s + (st * 2 + 0) * PLANE;
        const uint32_t sAl = s0s + (st * 2 + 1) * PLANE;
        const uint32_t sBh = s0s + 4 * PLANE + (st * 2 + 0) * PLANE;
        const uint32_t sBl = s0s + 4 * PLANE + (st * 2 + 1) * PLANE;

#pragma unroll
        for (int kk = 0; kk < 32; kk += 16) {
            uint32_t ah[4][4], al[4][4], bh[4][2], bl[4][2];
#pragma unroll
            for (int i = 0; i < 4; i++) {
                uint32_t aoff = (uint32_t)(((rA + i * 16 + arow) * GK2 + kk + acol) * 2);
                ldsm_x4(ah[i], sAh + aoff);
                ldsm_x4(al[i], sAl + aoff);
            }
#pragma unroll
            for (int jp = 0; jp < 2; jp++) {
                uint32_t boff = (uint32_t)(((cB + jp * 16 + brow) * GK2 + kk + bcol) * 2);
                uint32_t t[4];
                ldsm_x4(t, sBh + boff);
                bh[jp * 2][0] = t[0]; bh[jp * 2][1] = t[1];
                bh[jp * 2 + 1][0] = t[2]; bh[jp * 2 + 1][1] = t[3];
                ldsm_x4(t, sBl + boff);
                bl[jp * 2][0] = t[0]; bl[jp * 2][1] = t[1];
                bl[jp * 2 + 1][0] = t[2]; bl[jp * 2 + 1][1] = t[3];
            }
#pragma unroll
            for (int i = 0; i < 4; i++)
#pragma unroll
                for (int j = 0; j < 4; j++) {
                    mma16816(acc[i][j], ah[i], bh[j]);
                    mma16816(acc[i][j], ah[i], bl[j]);
                    mma16816(acc[i][j], al[i], bh[j]);
                }
        }
        __syncthreads();
    }

    auto epi2 = [&](long row, int col, float v0, float v1) {
        v0 += bias[col]; v1 += bias[col + 1];
        if (EPI == 0) {
            out[row * (long)ldc + col]     = v0;
            out[row * (long)ldc + col + 1] = v1;
        } else if (EPI == 1) {
            float s0 = 1.f / (1.f + __expf(-v0));
            float s1 = 1.f / (1.f + __expf(-v1));
            if (col < 1024) {
                out[row * 1024 + col]     = s0;
                out[row * 1024 + col + 1] = s1;
            } else {
                int d = col - 1024;
                float rx0 = s0 * X[row * 1024 + d];
                float rx1 = s1 * X[row * 1024 + d + 1];
                __nv_bfloat16 h0 = __float2bfloat16(rx0);
                __nv_bfloat16 h1 = __float2bfloat16(rx1);
                __nv_bfloat162 hp; hp.x = h0; hp.y = h1;
                __nv_bfloat162 lp;
                lp.x = __float2bfloat16(rx0 - __bfloat162float(h0));
                lp.y = __float2bfloat16(rx1 - __bfloat162float(h1));
                *(__nv_bfloat162*)&g_RX_hi[row * 1024 + d] = hp;
                *(__nv_bfloat162*)&g_RX_lo[row * 1024 + d] = lp;
            }
        } else {
            float hc0 = tanhf(v0), hc1 = tanhf(v1);
            float x0 = X[row * 1024 + col], x1 = X[row * 1024 + col + 1];
            out[row * 1024 + col]     = x0 + UD[row * 1024 + col] * (hc0 - x0);
            out[row * 1024 + col + 1] = x1 + UD[row * 1024 + col + 1] * (hc1 - x1);
        }
    };

#pragma unroll
    for (int i = 0; i < 4; i++) {
        long r = row0 + rA + i * 16 + g;
#pragma unroll
        for (int j = 0; j < 4; j++) {
            int cc = col0 + cB + j * 8 + tig * 2;
            epi2(r,     cc, acc[i][j][0], acc[i][j][1]);
            epi2(r + 8, cc, acc[i][j][2], acc[i][j][3]);
        }
    }
}

// ---------------- scan init --------------------------------------------------
__global__ void scan_init(const float* __restrict__ prev_ht)
{
    int i = blockIdx.x * 256 + threadIdx.x;   // 32768
    if (i == 0) g_barcnt = 0;
    float v = prev_ht[i];
    g_hcur[i] = v;
    __nv_bfloat16 hi = __float2bfloat16(v);
    g_h_hi[i] = hi;
    g_h_lo[i] = __float2bfloat16(v - __bfloat162float(hi));
}

__device__ __forceinline__ void gridbar(unsigned target)
{
    __syncthreads();
    if (threadIdx.x == 0) {
        asm volatile("red.release.gpu.global.add.u32 [%0], 1;"
                     :: "l"(&g_barcnt) : "memory");
        unsigned v;
        do {
            asm volatile("ld.acquire.gpu.global.u32 %0, [%1];"
                         : "=r"(v) : "l"(&g_barcnt) : "memory");
        } while (v < target);
    }
    __syncthreads();
}

// ---------------- persistent tensor-core scan (3-buffer cp.async ring) -------
// (identical to the proven 7706us round-8 version)
extern __shared__ __align__(16) char dsraw[];
__global__ void __launch_bounds__(256, 1)
scan_persistent()
{
    __nv_bfloat16* ws1h = (__nv_bfloat16*)dsraw;
    __nv_bfloat16* ws1l = ws1h + 16 * WSP;
    __nv_bfloat16* ws2h = ws1l + 16 * WSP;
    __nv_bfloat16* ws2l = ws2h + 8 * WSP;
    __nv_bfloat16* hbuf = ws2l + 8 * WSP;       // 3 bufs x [hi|lo] x 32*HSP
    float* red = (float*)(hbuf + 3 * 2 * 32 * HSP);

    const int tid = threadIdx.x, bx = blockIdx.x;
    const int lane = tid & 31, warp = tid >> 5;
    const int g = lane >> 2, tig = lane & 3;

#pragma unroll
    for (int s = 0; s < 8; s++) {
        int f = tid + s * 256;
        int c = f >> 7, q = (f & 127) * 8;
        *(uint4*)(ws1h + c * WSP + q) = *(const uint4*)&g_Wt_hi[(long)(bx * 16 + c) * 2048 + 1024 + q];
        *(uint4*)(ws1l + c * WSP + q) = *(const uint4*)&g_Wt_lo[(long)(bx * 16 + c) * 2048 + 1024 + q];
    }
#pragma unroll
    for (int s = 0; s < 4; s++) {
        int f = tid + s * 256;
        int c = f >> 7, q = (f & 127) * 8;
        *(uint4*)(ws2h + c * WSP + q) = *(const uint4*)&g_Wt_hi[(long)(2048 + bx * 8 + c) * 2048 + 1024 + q];
        *(uint4*)(ws2l + c * WSP + q) = *(const uint4*)&g_Wt_lo[(long)(2048 + bx * 8 + c) * 2048 + 1024 + q];
    }
    __syncthreads();

    const int o1 = tid * 2;
    const int r1 = o1 >> 4, c1 = o1 & 15;
    const int col1 = bx * 16 + c1;
    const int r2 = tid >> 3, c2 = tid & 7;
    const int d2 = bx * 8 + c2;

    const int sr[4] = { tid >> 5, (tid + 256) >> 5, (tid + 512) >> 5, (tid + 768) >> 5 };
    const int sq = (tid & 31) * 8;

    auto BUF_H = [&](int b) { return hbuf + (b * 2 + 0) * 32 * HSP; };
    auto BUF_L = [&](int b) { return hbuf + (b * 2 + 1) * 32 * HSP; };

    auto ISSUE = [&](const __nv_bfloat16* srcH, const __nv_bfloat16* srcL,
                     int ch, int buf) {
        __nv_bfloat16* dh = BUF_H(buf);
        __nv_bfloat16* dl = BUF_L(buf);
        int kc = ch * 256;
#pragma unroll
        for (int s = 0; s < 4; s++) {
            int r = sr[s];
            cpa16(dh + r * HSP + sq, srcH + r * 1024 + kc + sq);
            cpa16(dl + r * HSP + sq, srcL + r * 1024 + kc + sq);
        }
        CPA_COMMIT;
    };

    unsigned tgt = NB;

    for (int t = 0; t < TT; t++) {
        ISSUE(g_h_hi, g_h_lo, 0, 0);
        ISSUE(g_h_hi, g_h_lo, 1, 1);

        float2 g1 = *(const float2*)&g_gates[((long)r1 * TT + t) * 3072 + col1];
        float2 hv1 = make_float2(0.f, 0.f);
        if (col1 >= 1024)
            hv1 = __ldcg((const float2*)&g_hcur[r1 * 1024 + (col1 - 1024)]);
        float gg2 = g_gates[((long)r2 * TT + t) * 3072 + 2048 + d2];
        float hp = __ldcg(&g_hcur[r2 * 1024 + d2]);

        // ================= phase 1 =================
        float acc[2][2][4];
#pragma unroll
        for (int i = 0; i < 2; i++)
#pragma unroll
            for (int j = 0; j < 2; j++)
#pragma unroll
                for (int e = 0; e < 4; e++) acc[i][j][e] = 0.f;

#pragma unroll
        for (int ch = 0; ch < 4; ch++) {
            if (ch < 3) CPA_WAIT(1); else CPA_WAIT(0);
            __syncthreads();
            if (ch < 2) ISSUE(g_h_hi, g_h_lo, ch + 2, (ch + 2) % 3);
            const __nv_bfloat16* Ah = BUF_H(ch % 3);
            const __nv_bfloat16* Al = BUF_L(ch % 3);
#pragma unroll
            for (int kk = 0; kk < 32; kk += 16) {
                int kl = warp * 32 + kk + tig * 2;
                int kg = ch * 256 + kl;
                uint32_t ah[2][4], al[2][4], bh[2][2], bl[2][2];
#pragma unroll
                for (int i = 0; i < 2; i++) {
                    int r = i * 16 + g;
                    ah[i][0] = *(const uint32_t*)&Ah[r * HSP + kl];
                    ah[i][1] = *(const uint32_t*)&Ah[(r + 8) * HSP + kl];
                    ah[i][2] = *(const uint32_t*)&Ah[r * HSP + kl + 8];
                    ah[i][3] = *(const uint32_t*)&Ah[(r + 8) * HSP + kl + 8];
                    al[i][0] = *(const uint32_t*)&Al[r * HSP + kl];
                    al[i][1] = *(const uint32_t*)&Al[(r + 8) * HSP + kl];
                    al[i][2] = *(const uint32_t*)&Al[r * HSP + kl + 8];
                    al[i][3] = *(const uint32_t*)&Al[(r + 8) * HSP + kl + 8];
                }
#pragma unroll
                for (int j = 0; j < 2; j++) {
                    int n = j * 8 + g;
                    bh[j][0] = *(const uint32_t*)&ws1h[n * WSP + kg];
                    bh[j][1] = *(const uint32_t*)&ws1h[n * WSP + kg + 8];
                    bl[j][0] = *(const uint32_t*)&ws1l[n * WSP + kg];
                    bl[j][1] = *(const uint32_t*)&ws1l[n * WSP + kg + 8];
                }
#pragma unroll
                for (int i = 0; i < 2; i++)
#pragma unroll
                    for (int j = 0; j < 2; j++) {
                        mma16816(acc[i][j], ah[i], bh[j]);
                        mma16816(acc[i][j], ah[i], bl[j]);
                        mma16816(acc[i][j], al[i], bh[j]);
                    }
            }
        }
#pragma unroll
        for (int i = 0; i < 2; i++)
#pragma unroll
            for (int j = 0; j < 2; j++) {
                int r = i * 16 + g, c = j * 8 + tig * 2;
                red[warp * 512 + r * 16 + c]           = acc[i][j][0];
                red[warp * 512 + r * 16 + c + 1]       = acc[i][j][1];
                red[warp * 512 + (r + 8) * 16 + c]     = acc[i][j][2];
                red[warp * 512 + (r + 8) * 16 + c + 1] = acc[i][j][3];
            }
        __syncthreads();
        {
            float v0 = g1.x, v1 = g1.y;
#pragma unroll
            for (int w = 0; w < 8; w++) {
                float2 p = *(const float2*)&red[w * 512 + o1];
                v0 += p.x; v1 += p.y;
            }
            float s0 = 1.f / (1.f + __expf(-v0));
            float s1 = 1.f / (1.f + __expf(-v1));
            if (col1 < 1024) {
                *(float2*)&g_U[r1 * 1024 + col1] = make_float2(s0, s1);
            } else {
                int d = col1 - 1024;
                float rh0 = s0 * hv1.x, rh1 = s1 * hv1.y;
                __nv_bfloat16 h0 = __float2bfloat16(rh0);
                __nv_bfloat16 h1 = __float2bfloat16(rh1);
                __nv_bfloat162 hip; hip.x = h0; hip.y = h1;
                __nv_bfloat162 lop;
                lop.x = __float2bfloat16(rh0 - __bfloat162float(h0));
                lop.y = __float2bfloat16(rh1 - __bfloat162float(h1));
                *(__nv_bfloat162*)&g_rh_hi[r1 * 1024 + d] = hip;
                *(__nv_bfloat162*)&g_rh_lo[r1 * 1024 + d] = lop;
            }
        }

        gridbar(tgt); tgt += NB;

        // ================= phase 2 =================
        ISSUE(g_rh_hi, g_rh_lo, 0, 0);
        ISSUE(g_rh_hi, g_rh_lo, 1, 1);
        float uu = __ldcg(&g_U[r2 * 1024 + d2]);

        float acc2[2][4];
#pragma unroll
        for (int i = 0; i < 2; i++)
#pragma unroll
            for (int e = 0; e < 4; e++) acc2[i][e] = 0.f;

#pragma unroll
        for (int ch = 0; ch < 4; ch++) {
            if (ch < 3) CPA_WAIT(1); else CPA_WAIT(0);
            __syncthreads();
            if (ch < 2) ISSUE(g_rh_hi, g_rh_lo, ch + 2, (ch + 2) % 3);
            const __nv_bfloat16* Ah = BUF_H(ch % 3);
            const __nv_bfloat16* Al = BUF_L(ch % 3);
#pragma unroll
            for (int kk = 0; kk < 32; kk += 16) {
                int kl = warp * 32 + kk + tig * 2;
                int kg = ch * 256 + kl;
                uint32_t ah[2][4], al[2][4], bh[2], bl[2];
#pragma unroll
                for (int i = 0; i < 2; i++) {
                    int r = i * 16 + g;
                    ah[i][0] = *(const uint32_t*)&Ah[r * HSP + kl];
                    ah[i][1] = *(const uint32_t*)&Ah[(r + 8) * HSP + kl];
                    ah[i][2] = *(const uint32_t*)&Ah[r * HSP + kl + 8];
                    ah[i][3] = *(const uint32_t*)&Ah[(r + 8) * HSP + kl + 8];
                    al[i][0] = *(const uint32_t*)&Al[r * HSP + kl];
                    al[i][1] = *(const uint32_t*)&Al[(r + 8) * HSP + kl];
                    al[i][2] = *(const uint32_t*)&Al[r * HSP + kl + 8];
                    al[i][3] = *(const uint32_t*)&Al[(r + 8) * HSP + kl + 8];
                }
                {
                    int n = g;
                    bh[0] = *(const uint32_t*)&ws2h[n * WSP + kg];
                    bh[1] = *(const uint32_t*)&ws2h[n * WSP + kg + 8];
                    bl[0] = *(const uint32_t*)&ws2l[n * WSP + kg];
                    bl[1] = *(const uint32_t*)&ws2l[n * WSP + kg + 8];
                }
#pragma unroll
                for (int i = 0; i < 2; i++) {
                    mma16816(acc2[i], ah[i], bh);
                    mma16816(acc2[i], ah[i], bl);
                    mma16816(acc2[i], al[i], bh);
                }
            }
        }
#pragma unroll
        for (int i = 0; i < 2; i++) {
            int r = i * 16 + g, c = tig * 2;
            red[warp * 256 + r * 8 + c]           = acc2[i][0];
            red[warp * 256 + r * 8 + c + 1]       = acc2[i][1];
            red[warp * 256 + (r + 8) * 8 + c]     = acc2[i][2];
            red[warp * 256 + (r + 8) * 8 + c + 1] = acc2[i][3];
        }
        __syncthreads();
        {
            float v = gg2;
#pragma unroll
            for (int w = 0; w < 8; w++) v += red[w * 256 + tid];
            float hc = tanhf(v);
            float hn = hp + uu * (hc - hp);
            g_hcur[r2 * 1024 + d2] = hn;
            __nv_bfloat16 hi = __float2bfloat16(hn);
            __nv_bfloat16 lo = __float2bfloat16(hn - __bfloat162float(hi));
            g_h_hi[r2 * 1024 + d2] = hi;
            g_h_lo[r2 * 1024 + d2] = lo;
            long ho = ((long)r2 * TT + t) * 1024 + d2;
            g_HT_hi[ho] = hi;
            g_HT_lo[ho] = lo;
        }

        gridbar(tgt); tgt += NB;
    }
}

__global__ void copy_last(float* __restrict__ out)
{
    int i = blockIdx.x * 256 + threadIdx.x;   // 32768
    out[i] = g_hcur[i];
}

// ---------------- launch ------------------------------------------------------
#define SCAN_SMEM ((48*WSP + 3*2*32*HSP) * 2 + 8*512*4)
#define GEMM_SMEM (2 * 2 * 2 * 128 * GK2 * 2)

extern "C" void kernel_launch(void* const* d_in, const int* in_sizes, int n_in,
                              void* d_out, int out_size)
{
    const float* x       = (const float*)d_in[0];
    const float* prev_ht = (const float*)d_in[1];
    const float* weight  = (const float*)d_in[2];
    const float* bias    = (const float*)d_in[3];
    float* out = (float*)d_out;

    float *G, *UD;
    __nv_bfloat16 *Wth, *Wtl, *Xh, *Xl, *HTh, *HTl, *RXh, *RXl;
    cudaGetSymbolAddress((void**)&G,   g_gates);
    cudaGetSymbolAddress((void**)&UD,  g_UD);
    cudaGetSymbolAddress((void**)&Wth, g_Wt_hi);
    cudaGetSymbolAddress((void**)&Wtl, g_Wt_lo);
    cudaGetSymbolAddress((void**)&Xh,  g_X_hi);
    cudaGetSymbolAddress((void**)&Xl,  g_X_lo);
    cudaGetSymbolAddress((void**)&HTh, g_HT_hi);
    cudaGetSymbolAddress((void**)&HTl, g_HT_lo);
    cudaGetSymbolAddress((void**)&RXh, g_RX_hi);
    cudaGetSymbolAddress((void**)&RXl, g_RX_lo);

    static int attr_set = 0;
    if (!attr_set) {
        cudaFuncSetAttribute(scan_persistent,
                             cudaFuncAttributeMaxDynamicSharedMemorySize, SCAN_SMEM);
        cudaFuncSetAttribute(mma_gemm<0>,
                             cudaFuncAttributeMaxDynamicSharedMemorySize, GEMM_SMEM);
        cudaFuncSetAttribute(mma_gemm<1>,
                             cudaFuncAttributeMaxDynamicSharedMemorySize, GEMM_SMEM);
        cudaFuncSetAttribute(mma_gemm<2>,
                             cudaFuncAttributeMaxDynamicSharedMemorySize, GEMM_SMEM);
        attr_set = 1;
    }

    // prep: split W (transposed) and x into bf16 hi/lo
    conv_w_kernel<<<dim3(2048 / 64, 6144 / 64), 256>>>(weight);
    conv_x_kernel<<<MROWS * DD / 8 / 256, 256>>>(x);

    // gates = x @ Wxt + bt
    mma_gemm<0><<<dim3(3072 / 128, MROWS / 128), 256, GEMM_SMEM>>>(
        Xh, Xl, Xh, Xl, Wth, Wtl, bias, nullptr, G, nullptr, 1024, 3072);

    // scan
    scan_init<<<128, 256>>>(prev_ht);
    scan_persistent<<<NB, 256, SCAN_SMEM>>>();

    // F1: sigmoid(bd[:2D] + [x|ht] @ W[:,3072:5120]) -> UD, RX
    mma_gemm<1><<<dim3(2048 / 128, MROWS / 128), 256, GEMM_SMEM>>>(
        Xh, Xl, HTh, HTl, Wth + (size_t)3072 * 2048, Wtl + (size_t)3072 * 2048,
        bias + 3072, x, UD, nullptr, 2048, 2048);

    // F2: tanh(bd[2D:] + [rd*x|ht] @ W[:,5120:6144]); out = x + ud*(hc-x)
    mma_gemm<2><<<dim3(1024 / 128, MROWS / 128), 256, GEMM_SMEM>>>(
        RXh, RXl, HTh, HTl, Wth + (size_t)5120 * 2048, Wtl + (size_t)5120 * 2048,
        bias + 5120, x, out, UD, 2048, 1024);

    // last_ht
    copy_last<<<128, 256>>>(out + (size_t)MROWS * 1024);
}

// round 13
// speedup vs baseline: 1.2318x; 1.0006x over previous
#include <cuda_runtime.h>
#include <cuda_bf16.h>
#include <math.h>
#include <stdint.h>

// GridGRU: N=32, T=512, D=1024, H=1024
// inputs: x (N,T,D), prev_ht (N,H), weight (2048,6144), bias (6144)
// outputs: h (N,T,D) then last_ht (N,H), concatenated in d_out.

#define NN 32
#define TT 512
#define DD 1024
#define HH 1024
#define MROWS (NN*TT)        // 16384
#define WLD 6144
#define NB 128               // persistent scan blocks
#define GK2 40               // gemm smem k stride (bf16); 80B rows (16B-multiple)
#define WSP 1032             // scan weight smem k stride
#define HSP 264              // scan activation smem k stride

// ---------------- scratch (device globals) -----------------------------------
__device__ float g_gates[(size_t)MROWS * 3072];        // 192 MB
__device__ float g_hcur[NN * HH];
__device__ float g_U[NN * HH];
__device__ float g_UD[(size_t)MROWS * DD];             // 64 MB
__device__ __nv_bfloat16 g_Wt_hi[(size_t)6144 * 2048]; // transposed [col][k]
__device__ __nv_bfloat16 g_Wt_lo[(size_t)6144 * 2048];
__device__ __nv_bfloat16 g_X_hi[(size_t)MROWS * DD], g_X_lo[(size_t)MROWS * DD];
__device__ __nv_bfloat16 g_HT_hi[(size_t)MROWS * HH], g_HT_lo[(size_t)MROWS * HH];
__device__ __nv_bfloat16 g_RX_hi[(size_t)MROWS * DD], g_RX_lo[(size_t)MROWS * DD];
__device__ __nv_bfloat16 g_h_hi[NN * HH], g_h_lo[NN * HH];
__device__ __nv_bfloat16 g_rh_hi[NN * HH], g_rh_lo[NN * HH];
__device__ unsigned g_barcnt;

__device__ __forceinline__ void mma16816(float* c, const uint32_t* a, const uint32_t* b)
{
    asm volatile(
        "mma.sync.aligned.m16n8k16.row.col.f32.bf16.bf16.f32 "
        "{%0,%1,%2,%3}, {%4,%5,%6,%7}, {%8,%9}, {%0,%1,%2,%3};\n"
        : "+f"(c[0]), "+f"(c[1]), "+f"(c[2]), "+f"(c[3])
        : "r"(a[0]), "r"(a[1]), "r"(a[2]), "r"(a[3]), "r"(b[0]), "r"(b[1]));
}

__device__ __forceinline__ void ldsm_x4(uint32_t* r, uint32_t saddr)
{
    asm volatile("ldmatrix.sync.aligned.m8n8.x4.shared.b16 {%0,%1,%2,%3}, [%4];\n"
                 : "=r"(r[0]), "=r"(r[1]), "=r"(r[2]), "=r"(r[3]) : "r"(saddr));
}

__device__ __forceinline__ void cpa16(void* smem, const void* g)
{
    uint32_t a = (uint32_t)__cvta_generic_to_shared(smem);
    asm volatile("cp.async.cg.shared.global [%0], [%1], 16;" :: "r"(a), "l"(g));
}
#define CPA_COMMIT asm volatile("cp.async.commit_group;" ::: "memory")
#define CPA_WAIT(n) asm volatile("cp.async.wait_group %0;" :: "n"(n) : "memory")

// ---------------- prep: split x to bf16 hi/lo --------------------------------
__global__ void conv_x_kernel(const float* __restrict__ x)
{
    long i = ((long)blockIdx.x * 256 + threadIdx.x) * 8;
    float4 v0 = *(const float4*)(x + i);
    float4 v1 = *(const float4*)(x + i + 4);
    float v[8] = {v0.x, v0.y, v0.z, v0.w, v1.x, v1.y, v1.z, v1.w};
    __align__(16) __nv_bfloat16 hb[8], lb[8];
#pragma unroll
    for (int e = 0; e < 8; e++) {
        __nv_bfloat16 h = __float2bfloat16(v[e]);
        hb[e] = h;
        lb[e] = __float2bfloat16(v[e] - __bfloat162float(h));
    }
    *(uint4*)&g_X_hi[i] = *(uint4*)hb;
    *(uint4*)&g_X_lo[i] = *(uint4*)lb;
}

// ---------------- prep: split + transpose weight to [col][k] bf16 ------------
__global__ void conv_w_kernel(const float* __restrict__ W)
{
    __shared__ float ws[64][65];
    const int k0 = blockIdx.x * 64, c0 = blockIdx.y * 64;
    const int tid = threadIdx.x;
#pragma unroll
    for (int s = 0; s < 4; s++) {
        int f = tid + s * 256;
        int kr = f >> 4, cc = (f & 15) * 4;
        float4 v = *(const float4*)(W + (long)(k0 + kr) * WLD + c0 + cc);
        ws[kr][cc] = v.x; ws[kr][cc + 1] = v.y; ws[kr][cc + 2] = v.z; ws[kr][cc + 3] = v.w;
    }
    __syncthreads();
    const int col = tid & 63, kq = tid >> 6;
    __align__(16) __nv_bfloat16 hb[16], lb[16];
#pragma unroll
    for (int j = 0; j < 16; j++) {
        float v = ws[kq * 16 + j][col];
        __nv_bfloat16 h = __float2bfloat16(v);
        hb[j] = h;
        lb[j] = __float2bfloat16(v - __bfloat162float(h));
    }
    long dst = (long)(c0 + col) * 2048 + k0 + kq * 16;
    ((uint4*)&g_Wt_hi[dst])[0] = ((uint4*)hb)[0];
    ((uint4*)&g_Wt_hi[dst])[1] = ((uint4*)hb)[1];
    ((uint4*)&g_Wt_lo[dst])[0] = ((uint4*)lb)[0];
    ((uint4*)&g_Wt_lo[dst])[1] = ((uint4*)lb)[1];
}

// ---------------- big GEMM: bf16 hi/lo, cp.async + ldmatrix ------------------
template<int EPI>
__global__ void __launch_bounds__(256, 2)
mma_gemm(const __nv_bfloat16* __restrict__ A0h, const __nv_bfloat16* __restrict__ A0l,
         const __nv_bfloat16* __restrict__ A1h, const __nv_bfloat16* __restrict__ A1l,
         const __nv_bfloat16* __restrict__ Bth, const __nv_bfloat16* __restrict__ Btl,
         const float* __restrict__ bias, const float* __restrict__ X,
         float* __restrict__ out, const float* __restrict__ UD,
         int K, int ldc)
{
    extern __shared__ __align__(16) char gsm[];
    __nv_bfloat16* As = (__nv_bfloat16*)gsm;        // [stage][hi/lo][128*GK2]
    __nv_bfloat16* Bs = As + 2 * 2 * 128 * GK2;
    const uint32_t s0s = (uint32_t)__cvta_generic_to_shared(gsm);
    const uint32_t PLANE = 128 * GK2 * 2;           // bytes per plane

    const int tid = threadIdx.x, lane = tid & 31, warp = tid >> 5;
    const int warpM = warp & 1, warpN = warp >> 1;
    const int g = lane >> 2, tig = lane & 3;
    const int row0 = blockIdx.y * 128, col0 = blockIdx.x * 128;
    const int rA = warpM * 64, cB = warpN * 32;
    const int r0 = tid >> 2, kq = (tid & 3) * 8;
    const int r1 = r0 + 64;

    // ldmatrix lane address components (aligned: 40 bf16 = 80 B = 5*16 B rows)
    const int arow = ((lane >> 3) & 1) * 8 + (lane & 7);
    const int acol = (lane >> 4) * 8;
    const int brow = (lane >> 4) * 8 + (lane & 7);
    const int bcol = ((lane >> 3) & 1) * 8;

    float acc[4][4][4];
#pragma unroll
    for (int i = 0; i < 4; i++)
#pragma unroll
        for (int j = 0; j < 4; j++)
#pragma unroll
            for (int e = 0; e < 4; e++) acc[i][j][e] = 0.f;

    auto ISSUE = [&](int k0, int st) {
        const __nv_bfloat16 *ph, *pl; int kb;
        if (k0 < 1024) { ph = A0h; pl = A0l; kb = k0; }
        else           { ph = A1h; pl = A1l; kb = k0 - 1024; }
        __nv_bfloat16* Ah = As + (st * 2 + 0) * 128 * GK2;
        __nv_bfloat16* Al = As + (st * 2 + 1) * 128 * GK2;
        __nv_bfloat16* Bh = Bs + (st * 2 + 0) * 128 * GK2;
        __nv_bfloat16* Bl = Bs + (st * 2 + 1) * 128 * GK2;
        cpa16(Ah + r0 * GK2 + kq, ph + (long)(row0 + r0) * 1024 + kb + kq);
        cpa16(Ah + r1 * GK2 + kq, ph + (long)(row0 + r1) * 1024 + kb + kq);
        cpa16(Al + r0 * GK2 + kq, pl + (long)(row0 + r0) * 1024 + kb + kq);
        cpa16(Al + r1 * GK2 + kq, pl + (long)(row0 + r1) * 1024 + kb + kq);
        cpa16(Bh + r0 * GK2 + kq, Bth + (long)(col0 + r0) * 2048 + k0 + kq);
        cpa16(Bh + r1 * GK2 + kq, Bth + (long)(col0 + r1) * 2048 + k0 + kq);
        cpa16(Bl + r0 * GK2 + kq, Btl + (long)(col0 + r0) * 2048 + k0 + kq);
        cpa16(Bl + r1 * GK2 + kq, Btl + (long)(col0 + r1) * 2048 + k0 + kq);
    };

    const int KT = K / 32;
    ISSUE(0, 0); CPA_COMMIT;

    for (int kt = 0; kt < KT; kt++) {
        const int st = kt & 1;
        if (kt + 1 < KT) { ISSUE((kt + 1) * 32, st ^ 1); CPA_COMMIT; CPA_WAIT(1); }
        else             { CPA_WAIT(0); }
        __syncthreads();

        const uint32_t sAh = s0s + (st * 2 + 0) * PLANE;
        const uint32_t sAl = s0s + (st * 2 + 1) * PLANE;
        const uint32_t sBh = s0s + 4 * PLANE + (st * 2 + 0) * PLANE;
        const uint32_t sBl = s0s + 4 * PLANE + (st * 2 + 1) * PLANE;

#pragma unroll
        for (int kk = 0; kk < 32; kk += 16) {
            uint32_t ah[4][4], al[4][4], bh[4][2], bl[4][2];
#pragma unroll
            for (int i = 0; i < 4; i++) {
                uint32_t aoff = (uint32_t)(((rA + i * 16 + arow) * GK2 + kk + acol) * 2);
                ldsm_x4(ah[i], sAh + aoff);
                ldsm_x4(al[i], sAl + aoff);
            }
#pragma unroll
            for (int jp = 0; jp < 2; jp++) {
                uint32_t boff = (uint32_t)(((cB + jp * 16 + brow) * GK2 + kk + bcol) * 2);
                uint32_t t[4];
                ldsm_x4(t, sBh + boff);
                bh[jp * 2][0] = t[0]; bh[jp * 2][1] = t[1];
                bh[jp * 2 + 1][0] = t[2]; bh[jp * 2 + 1][1] = t[3];
                ldsm_x4(t, sBl + boff);
                bl[jp * 2][0] = t[0]; bl[jp * 2][1] = t[1];
                bl[jp * 2 + 1][0] = t[2]; bl[jp * 2 + 1][1] = t[3];
            }
#pragma unroll
            for (int i = 0; i < 4; i++)
#pragma unroll
                for (int j = 0; j < 4; j++) {
                    mma16816(acc[i][j], ah[i], bh[j]);
                    mma16816(acc[i][j], ah[i], bl[j]);
                    mma16816(acc[i][j], al[i], bh[j]);
                }
        }
        __syncthreads();
    }

    auto epi2 = [&](long row, int col, float v0, float v1) {
        v0 += bias[col]; v1 += bias[col + 1];
        if (EPI == 0) {
            out[row * (long)ldc + col]     = v0;
            out[row * (long)ldc + col + 1] = v1;
        } else if (EPI == 1) {
            float s0 = 1.f / (1.f + __expf(-v0));
            float s1 = 1.f / (1.f + __expf(-v1));
            if (col < 1024) {
                out[row * 1024 + col]     = s0;
                out[row * 1024 + col + 1] = s1;
            } else {
                int d = col - 1024;
                float rx0 = s0 * X[row * 1024 + d];
                float rx1 = s1 * X[row * 1024 + d + 1];
                __nv_bfloat16 h0 = __float2bfloat16(rx0);
                __nv_bfloat16 h1 = __float2bfloat16(rx1);
                __nv_bfloat162 hp; hp.x = h0; hp.y = h1;
                __nv_bfloat162 lp;
                lp.x = __float2bfloat16(rx0 - __bfloat162float(h0));
                lp.y = __float2bfloat16(rx1 - __bfloat162float(h1));
                *(__nv_bfloat162*)&g_RX_hi[row * 1024 + d] = hp;
                *(__nv_bfloat162*)&g_RX_lo[row * 1024 + d] = lp;
            }
        } else {
            float hc0 = tanhf(v0), hc1 = tanhf(v1);
            float x0 = X[row * 1024 + col], x1 = X[row * 1024 + col + 1];
            out[row * 1024 + col]     = x0 + UD[row * 1024 + col] * (hc0 - x0);
            out[row * 1024 + col + 1] = x1 + UD[row * 1024 + col + 1] * (hc1 - x1);
        }
    };

#pragma unroll
    for (int i = 0; i < 4; i++) {
        long r = row0 + rA + i * 16 + g;
#pragma unroll
        for (int j = 0; j < 4; j++) {
            int cc = col0 + cB + j * 8 + tig * 2;
            epi2(r,     cc, acc[i][j][0], acc[i][j][1]);
            epi2(r + 8, cc, acc[i][j][2], acc[i][j][3]);
        }
    }
}

// ---------------- scan init --------------------------------------------------
__global__ void scan_init(const float* __restrict__ prev_ht)
{
    int i = blockIdx.x * 256 + threadIdx.x;   // 32768
    if (i == 0) g_barcnt = 0;
    float v = prev_ht[i];
    g_hcur[i] = v;
    __nv_bfloat16 hi = __float2bfloat16(v);
    g_h_hi[i] = hi;
    g_h_lo[i] = __float2bfloat16(v - __bfloat162float(hi));
}

__device__ __forceinline__ void gridbar(unsigned target)
{
    __syncthreads();
    if (threadIdx.x == 0) {
        asm volatile("red.release.gpu.global.add.u32 [%0], 1;"
                     :: "l"(&g_barcnt) : "memory");
        unsigned v;
        do {
            asm volatile("ld.acquire.gpu.global.u32 %0, [%1];"
                         : "=r"(v) : "l"(&g_barcnt) : "memory");
        } while (v < target);
    }
    __syncthreads();
}

// ---------------- persistent tensor-core scan (3-buffer cp.async ring) -------
extern __shared__ __align__(16) char dsraw[];
__global__ void __launch_bounds__(256, 1)
scan_persistent()
{
    __nv_bfloat16* ws1h = (__nv_bfloat16*)dsraw;
    __nv_bfloat16* ws1l = ws1h + 16 * WSP;
    __nv_bfloat16* ws2h = ws1l + 16 * WSP;
    __nv_bfloat16* ws2l = ws2h + 8 * WSP;
    __nv_bfloat16* hbuf = ws2l + 8 * WSP;       // 3 bufs x [hi|lo] x 32*HSP
    float* red = (float*)(hbuf + 3 * 2 * 32 * HSP);

    const int tid = threadIdx.x, bx = blockIdx.x;
    const int lane = tid & 31, warp = tid >> 5;
    const int g = lane >> 2, tig = lane & 3;

#pragma unroll
    for (int s = 0; s < 8; s++) {
        int f = tid + s * 256;
        int c = f >> 7, q = (f & 127) * 8;
        *(uint4*)(ws1h + c * WSP + q) = *(const uint4*)&g_Wt_hi[(long)(bx * 16 + c) * 2048 + 1024 + q];
        *(uint4*)(ws1l + c * WSP + q) = *(const uint4*)&g_Wt_lo[(long)(bx * 16 + c) * 2048 + 1024 + q];
    }
#pragma unroll
    for (int s = 0; s < 4; s++) {
        int f = tid + s * 256;
        int c = f >> 7, q = (f & 127) * 8;
        *(uint4*)(ws2h + c * WSP + q) = *(const uint4*)&g_Wt_hi[(long)(2048 + bx * 8 + c) * 2048 + 1024 + q];
        *(uint4*)(ws2l + c * WSP + q) = *(const uint4*)&g_Wt_lo[(long)(2048 + bx * 8 + c) * 2048 + 1024 + q];
    }
    __syncthreads();

    const int o1 = tid * 2;
    const int r1 = o1 >> 4, c1 = o1 & 15;
    const int col1 = bx * 16 + c1;
    const int r2 = tid >> 3, c2 = tid & 7;
    const int d2 = bx * 8 + c2;

    const int sr[4] = { tid >> 5, (tid + 256) >> 5, (tid + 512) >> 5, (tid + 768) >> 5 };
    const int sq = (tid & 31) * 8;

    auto BUF_H = [&](int b) { return hbuf + (b * 2 + 0) * 32 * HSP; };
    auto BUF_L = [&](int b) { return hbuf + (b * 2 + 1) * 32 * HSP; };

    auto ISSUE = [&](const __nv_bfloat16* srcH, const __nv_bfloat16* srcL,
                     int ch, int buf) {
        __nv_bfloat16* dh = BUF_H(buf);
        __nv_bfloat16* dl = BUF_L(buf);
        int kc = ch * 256;
#pragma unroll
        for (int s = 0; s < 4; s++) {
            int r = sr[s];
            cpa16(dh + r * HSP + sq, srcH + r * 1024 + kc + sq);
            cpa16(dl + r * HSP + sq, srcL + r * 1024 + kc + sq);
        }
        CPA_COMMIT;
    };

    unsigned tgt = NB;

    for (int t = 0; t < TT; t++) {
        ISSUE(g_h_hi, g_h_lo, 0, 0);
        ISSUE(g_h_hi, g_h_lo, 1, 1);

        float2 g1 = *(const float2*)&g_gates[((long)r1 * TT + t) * 3072 + col1];
        float2 hv1 = make_float2(0.f, 0.f);
        if (col1 >= 1024)
            hv1 = __ldcg((const float2*)&g_hcur[r1 * 1024 + (col1 - 1024)]);
        float gg2 = g_gates[((long)r2 * TT + t) * 3072 + 2048 + d2];
        float hp = __ldcg(&g_hcur[r2 * 1024 + d2]);

        // ================= phase 1 =================
        float acc[2][2][4];
#pragma unroll
        for (int i = 0; i < 2; i++)
#pragma unroll
            for (int j = 0; j < 2; j++)
#pragma unroll
                for (int e = 0; e < 4; e++) acc[i][j][e] = 0.f;

#pragma unroll
        for (int ch = 0; ch < 4; ch++) {
            if (ch < 3) CPA_WAIT(1); else CPA_WAIT(0);
            __syncthreads();
            if (ch < 2) ISSUE(g_h_hi, g_h_lo, ch + 2, (ch + 2) % 3);
            const __nv_bfloat16* Ah = BUF_H(ch % 3);
            const __nv_bfloat16* Al = BUF_L(ch % 3);
#pragma unroll
            for (int kk = 0; kk < 32; kk += 16) {
                int kl = warp * 32 + kk + tig * 2;
                int kg = ch * 256 + kl;
                uint32_t ah[2][4], al[2][4], bh[2][2], bl[2][2];
#pragma unroll
                for (int i = 0; i < 2; i++) {
                    int r = i * 16 + g;
                    ah[i][0] = *(const uint32_t*)&Ah[r * HSP + kl];
                    ah[i][1] = *(const uint32_t*)&Ah[(r + 8) * HSP + kl];
                    ah[i][2] = *(const uint32_t*)&Ah[r * HSP + kl + 8];
                    ah[i][3] = *(const uint32_t*)&Ah[(r + 8) * HSP + kl + 8];
                    al[i][0] = *(const uint32_t*)&Al[r * HSP + kl];
                    al[i][1] = *(const uint32_t*)&Al[(r + 8) * HSP + kl];
                    al[i][2] = *(const uint32_t*)&Al[r * HSP + kl + 8];
                    al[i][3] = *(const uint32_t*)&Al[(r + 8) * HSP + kl + 8];
                }
#pragma unroll
                for (int j = 0; j < 2; j++) {
                    int n = j * 8 + g;
                    bh[j][0] = *(const uint32_t*)&ws1h[n * WSP + kg];
                    bh[j][1] = *(const uint32_t*)&ws1h[n * WSP + kg + 8];
                    bl[j][0] = *(const uint32_t*)&ws1l[n * WSP + kg];
                    bl[j][1] = *(const uint32_t*)&ws1l[n * WSP + kg + 8];
                }
#pragma unroll
                for (int i = 0; i < 2; i++)
#pragma unroll
                    for (int j = 0; j < 2; j++) {
                        mma16816(acc[i][j], ah[i], bh[j]);
                        mma16816(acc[i][j], ah[i], bl[j]);
                        mma16816(acc[i][j], al[i], bh[j]);
                    }
            }
        }
#pragma unroll
        for (int i = 0; i < 2; i++)
#pragma unroll
            for (int j = 0; j < 2; j++) {
                int r = i * 16 + g, c = j * 8 + tig * 2;
                red[warp * 512 + r * 16 + c]           = acc[i][j][0];
                red[warp * 512 + r * 16 + c + 1]       = acc[i][j][1];
                red[warp * 512 + (r + 8) * 16 + c]     = acc[i][j][2];
                red[warp * 512 + (r + 8) * 16 + c + 1] = acc[i][j][3];
            }
        __syncthreads();
        {
            float v0 = g1.x, v1 = g1.y;
#pragma unroll
            for (int w = 0; w < 8; w++) {
                float2 p = *(const float2*)&red[w * 512 + o1];
                v0 += p.x; v1 += p.y;
            }
            float s0 = 1.f / (1.f + __expf(-v0));
            float s1 = 1.f / (1.f + __expf(-v1));
            if (col1 < 1024) {
                *(float2*)&g_U[r1 * 1024 + col1] = make_float2(s0, s1);
            } else {
                int d = col1 - 1024;
                float rh0 = s0 * hv1.x, rh1 = s1 * hv1.y;
                __nv_bfloat16 h0 = __float2bfloat16(rh0);
                __nv_bfloat16 h1 = __float2bfloat16(rh1);
                __nv_bfloat162 hip; hip.x = h0; hip.y = h1;
                __nv_bfloat162 lop;
                lop.x = __float2bfloat16(rh0 - __bfloat162float(h0));
                lop.y = __float2bfloat16(rh1 - __bfloat162float(h1));
                *(__nv_bfloat162*)&g_rh_hi[r1 * 1024 + d] = hip;
                *(__nv_bfloat162*)&g_rh_lo[r1 * 1024 + d] = lop;
            }
        }

        gridbar(tgt); tgt += NB;

        // ================= phase 2 =================
        ISSUE(g_rh_hi, g_rh_lo, 0, 0);
        ISSUE(g_rh_hi, g_rh_lo, 1, 1);
        float uu = __ldcg(&g_U[r2 * 1024 + d2]);

        float acc2[2][4];
#pragma unroll
        for (int i = 0; i < 2; i++)
#pragma unroll
            for (int e = 0; e < 4; e++) acc2[i][e] = 0.f;

#pragma unroll
        for (int ch = 0; ch < 4; ch++) {
            if (ch < 3) CPA_WAIT(1); else CPA_WAIT(0);
            __syncthreads();
            if (ch < 2) ISSUE(g_rh_hi, g_rh_lo, ch + 2, (ch + 2) % 3);
            const __nv_bfloat16* Ah = BUF_H(ch % 3);
            const __nv_bfloat16* Al = BUF_L(ch % 3);
#pragma unroll
            for (int kk = 0; kk < 32; kk += 16) {
                int kl = warp * 32 + kk + tig * 2;
                int kg = ch * 256 + kl;
                uint32_t ah[2][4], al[2][4], bh[2], bl[2];
#pragma unroll
                for (int i = 0; i < 2; i++) {
                    int r = i * 16 + g;
                    ah[i][0] = *(const uint32_t*)&Ah[r * HSP + kl];
                    ah[i][1] = *(const uint32_t*)&Ah[(r + 8) * HSP + kl];
                    ah[i][2] = *(const uint32_t*)&Ah[r * HSP + kl + 8];
                    ah[i][3] = *(const uint32_t*)&Ah[(r + 8) * HSP + kl + 8];
                    al[i][0] = *(const uint32_t*)&Al[r * HSP + kl];
                    al[i][1] = *(const uint32_t*)&Al[(r + 8) * HSP + kl];
                    al[i][2] = *(const uint32_t*)&Al[r * HSP + kl + 8];
                    al[i][3] = *(const uint32_t*)&Al[(r + 8) * HSP + kl + 8];
                }
                {
                    int n = g;
                    bh[0] = *(const uint32_t*)&ws2h[n * WSP + kg];
                    bh[1] = *(const uint32_t*)&ws2h[n * WSP + kg + 8];
                    bl[0] = *(const uint32_t*)&ws2l[n * WSP + kg];
                    bl[1] = *(const uint32_t*)&ws2l[n * WSP + kg + 8];
                }
#pragma unroll
                for (int i = 0; i < 2; i++) {
                    mma16816(acc2[i], ah[i], bh);
                    mma16816(acc2[i], ah[i], bl);
                    mma16816(acc2[i], al[i], bh);
                }
            }
        }
#pragma unroll
        for (int i = 0; i < 2; i++) {
            int r = i * 16 + g, c = tig * 2;
            red[warp * 256 + r * 8 + c]           = acc2[i][0];
            red[warp * 256 + r * 8 + c + 1]       = acc2[i][1];
            red[warp * 256 + (r + 8) * 8 + c]     = acc2[i][2];
            red[warp * 256 + (r + 8) * 8 + c + 1] = acc2[i][3];
        }
        __syncthreads();
        {
            float v = gg2;
#pragma unroll
            for (int w = 0; w < 8; w++) v += red[w * 256 + tid];
            float hc = tanhf(v);
            float hn = hp + uu * (hc - hp);
            g_hcur[r2 * 1024 + d2] = hn;
            __nv_bfloat16 hi = __float2bfloat16(hn);
            __nv_bfloat16 lo = __float2bfloat16(hn - __bfloat162float(hi));
            g_h_hi[r2 * 1024 + d2] = hi;
            g_h_lo[r2 * 1024 + d2] = lo;
            long ho = ((long)r2 * TT + t) * 1024 + d2;
            g_HT_hi[ho] = hi;
            g_HT_lo[ho] = lo;
        }

        gridbar(tgt); tgt += NB;
    }
}

__global__ void copy_last(float* __restrict__ out)
{
    int i = blockIdx.x * 256 + threadIdx.x;   // 32768
    out[i] = g_hcur[i];
}

// ---------------- launch ------------------------------------------------------
#define SCAN_SMEM ((48*WSP + 3*2*32*HSP) * 2 + 8*512*4)
// As+Bs = 2 stages x (A hi/lo + B hi/lo) x 128 x GK2 bf16 = 81920 bytes.
// (Previous rounds requested 2x this, capping the GEMM at 1 CTA/SM.)
#define GEMM_SMEM (2 * 4 * 128 * GK2 * 2 / 2)   // = 2*2*128*GK2*2 bytes... kept explicit below
#undef GEMM_SMEM
#define GEMM_SMEM (2 /*stages*/ * 2 /*hi,lo*/ * 2 /*A,B*/ * 128 * GK2 * 2 /*B per bf16*/ / 2)
#undef GEMM_SMEM
#define GEMM_SMEM (4 * 128 * GK2 * 2 * 2)  // 4 planes/stage-pair... final: 81920 bytes
#undef GEMM_SMEM
#define GEMM_SMEM 81920

extern "C" void kernel_launch(void* const* d_in, const int* in_sizes, int n_in,
                              void* d_out, int out_size)
{
    const float* x       = (const float*)d_in[0];
    const float* prev_ht = (const float*)d_in[1];
    const float* weight  = (const float*)d_in[2];
    const float* bias    = (const float*)d_in[3];
    float* out = (float*)d_out;

    float *G, *UD;
    __nv_bfloat16 *Wth, *Wtl, *Xh, *Xl, *HTh, *HTl, *RXh, *RXl;
    cudaGetSymbolAddress((void**)&G,   g_gates);
    cudaGetSymbolAddress((void**)&UD,  g_UD);
    cudaGetSymbolAddress((void**)&Wth, g_Wt_hi);
    cudaGetSymbolAddress((void**)&Wtl, g_Wt_lo);
    cudaGetSymbolAddress((void**)&Xh,  g_X_hi);
    cudaGetSymbolAddress((void**)&Xl,  g_X_lo);
    cudaGetSymbolAddress((void**)&HTh, g_HT_hi);
    cudaGetSymbolAddress((void**)&HTl, g_HT_lo);
    cudaGetSymbolAddress((void**)&RXh, g_RX_hi);
    cudaGetSymbolAddress((void**)&RXl, g_RX_lo);

    static int attr_set = 0;
    if (!attr_set) {
        cudaFuncSetAttribute(scan_persistent,
                             cudaFuncAttributeMaxDynamicSharedMemorySize, SCAN_SMEM);
        cudaFuncSetAttribute(mma_gemm<0>,
                             cudaFuncAttributeMaxDynamicSharedMemorySize, GEMM_SMEM);
        cudaFuncSetAttribute(mma_gemm<1>,
                             cudaFuncAttributeMaxDynamicSharedMemorySize, GEMM_SMEM);
        cudaFuncSetAttribute(mma_gemm<2>,
                             cudaFuncAttributeMaxDynamicSharedMemorySize, GEMM_SMEM);
        attr_set = 1;
    }

    // prep: split W (transposed) and x into bf16 hi/lo
    conv_w_kernel<<<dim3(2048 / 64, 6144 / 64), 256>>>(weight);
    conv_x_kernel<<<MROWS * DD / 8 / 256, 256>>>(x);

    // gates = x @ Wxt + bt
    mma_gemm<0><<<dim3(3072 / 128, MROWS / 128), 256, GEMM_SMEM>>>(
        Xh, Xl, Xh, Xl, Wth, Wtl, bias, nullptr, G, nullptr, 1024, 3072);

    // scan
    scan_init<<<128, 256>>>(prev_ht);
    scan_persistent<<<NB, 256, SCAN_SMEM>>>();

    // F1: sigmoid(bd[:2D] + [x|ht] @ W[:,3072:5120]) -> UD, RX
    mma_gemm<1><<<dim3(2048 / 128, MROWS / 128), 256, GEMM_SMEM>>>(
        Xh, Xl, HTh, HTl, Wth + (size_t)3072 * 2048, Wtl + (size_t)3072 * 2048,
        bias + 3072, x, UD, nullptr, 2048, 2048);

    // F2: tanh(bd[2D:] + [rd*x|ht] @ W[:,5120:6144]); out = x + ud*(hc-x)
    mma_gemm<2><<<dim3(1024 / 128, MROWS / 128), 256, GEMM_SMEM>>>(
        RXh, RXl, HTh, HTl, Wth + (size_t)5120 * 2048, Wtl + (size_t)5120 * 2048,
        bias + 5120, x, out, UD, 2048, 1024);

    // last_ht
    copy_last<<<128, 256>>>(out + (size_t)MROWS * 1024);
}